// round 8
// baseline (speedup 1.0000x reference)
#include <cuda_runtime.h>
#include <math.h>

// Problem constants
#define BB 4
#define SS 2048
#define DD 1024
#define UU 1024

#define BM 128
#define BN 128
#define BK 8

// Scratch: Q, K, V, context — each [B,S,U] fp32 = 33.5 MB (device globals; no allocs)
static __device__ float g_q[(size_t)BB * SS * UU];
static __device__ float g_k[(size_t)BB * SS * UU];
static __device__ float g_v[(size_t)BB * SS * UU];
static __device__ float g_c[(size_t)BB * SS * UU];

// ---------------------------------------------------------------------------
// NN GEMM: C[M,N] = A[M,K] * B[K,N] (+ bias[N] if bias != nullptr)
// Row-major. 128x128 tile, BK=8, 256 threads, 8x8 per thread (4+4 split),
// double-buffered SMEM. Batched via blockIdx.z with element strides.
// Requires: M%128==0, N%128==0, K%8==0 (true for all call sites here).
// ---------------------------------------------------------------------------
__global__ __launch_bounds__(256, 2)
void gemm_nn_kernel(const float* __restrict__ A, const float* __restrict__ B,
                    float* __restrict__ C, const float* __restrict__ bias,
                    int M, int N, int K,
                    long long sA, long long sB, long long sC)
{
    A += (long long)blockIdx.z * sA;
    B += (long long)blockIdx.z * sB;
    C += (long long)blockIdx.z * sC;

    __shared__ float As[2][BK][BM];
    __shared__ float Bs[2][BK][BN];

    const int tid = threadIdx.x;
    const int m0 = blockIdx.y * BM;
    const int n0 = blockIdx.x * BN;

    // A tile loader: one float4 per thread, transposed store
    const int a_row = tid >> 1;            // 0..127
    const int a_col = (tid & 1) << 2;      // 0 or 4
    // B tile loader: one float4 per thread, direct store
    const int b_row = tid >> 5;            // 0..7
    const int b_col = (tid & 31) << 2;     // 0..124

    const int tx = tid & 15;               // output n sub-tile
    const int ty = tid >> 4;               // output m sub-tile

    float acc[8][8];
#pragma unroll
    for (int i = 0; i < 8; i++)
#pragma unroll
        for (int j = 0; j < 8; j++) acc[i][j] = 0.0f;

    const float* Aptr = A + (long long)(m0 + a_row) * K + a_col;
    const float* Bptr = B + (long long)b_row * N + (n0 + b_col);

    float4 areg = *(const float4*)Aptr;
    float4 breg = *(const float4*)Bptr;

    As[0][a_col + 0][a_row] = areg.x;
    As[0][a_col + 1][a_row] = areg.y;
    As[0][a_col + 2][a_row] = areg.z;
    As[0][a_col + 3][a_row] = areg.w;
    *(float4*)&Bs[0][b_row][b_col] = breg;
    __syncthreads();

    const int ntiles = K / BK;
    for (int t = 0; t < ntiles; t++) {
        const int buf = t & 1;
        if (t + 1 < ntiles) {
            areg = *(const float4*)(Aptr + (t + 1) * BK);
            breg = *(const float4*)(Bptr + (long long)(t + 1) * BK * N);
        }
        float ra[8], rb[8];
#pragma unroll
        for (int k = 0; k < BK; k++) {
            *(float4*)&ra[0] = *(const float4*)&As[buf][k][ty * 4];
            *(float4*)&ra[4] = *(const float4*)&As[buf][k][64 + ty * 4];
            *(float4*)&rb[0] = *(const float4*)&Bs[buf][k][tx * 4];
            *(float4*)&rb[4] = *(const float4*)&Bs[buf][k][64 + tx * 4];
#pragma unroll
            for (int i = 0; i < 8; i++)
#pragma unroll
                for (int j = 0; j < 8; j++)
                    acc[i][j] = fmaf(ra[i], rb[j], acc[i][j]);
        }
        if (t + 1 < ntiles) {
            const int nb = buf ^ 1;
            As[nb][a_col + 0][a_row] = areg.x;
            As[nb][a_col + 1][a_row] = areg.y;
            As[nb][a_col + 2][a_row] = areg.z;
            As[nb][a_col + 3][a_row] = areg.w;
            *(float4*)&Bs[nb][b_row][b_col] = breg;
            __syncthreads();
        }
    }

#pragma unroll
    for (int ih = 0; ih < 2; ih++)
#pragma unroll
        for (int ii = 0; ii < 4; ii++) {
            const int row = m0 + ih * 64 + ty * 4 + ii;
#pragma unroll
            for (int jh = 0; jh < 2; jh++) {
                const int col = n0 + jh * 64 + tx * 4;
                float4 v;
                v.x = acc[ih * 4 + ii][jh * 4 + 0];
                v.y = acc[ih * 4 + ii][jh * 4 + 1];
                v.z = acc[ih * 4 + ii][jh * 4 + 2];
                v.w = acc[ih * 4 + ii][jh * 4 + 3];
                if (bias != nullptr) {
                    v.x += bias[col + 0];
                    v.y += bias[col + 1];
                    v.z += bias[col + 2];
                    v.w += bias[col + 3];
                }
                *(float4*)(C + (long long)row * N + col) = v;
            }
        }
}

// ---------------------------------------------------------------------------
// NT GEMM (scaled): C[M,N] = (A[M,K] * B[N,K]^T) * (*scale)
// A, B both row-major K-contiguous (Q @ K^T pattern). Batched via blockIdx.z.
// ---------------------------------------------------------------------------
__global__ __launch_bounds__(256, 2)
void gemm_nt_scaled_kernel(const float* __restrict__ A, const float* __restrict__ B,
                           float* __restrict__ C, const float* __restrict__ scale_ptr,
                           int M, int N, int K,
                           long long sA, long long sB, long long sC)
{
    A += (long long)blockIdx.z * sA;
    B += (long long)blockIdx.z * sB;
    C += (long long)blockIdx.z * sC;

    __shared__ float As[2][BK][BM];
    __shared__ float Bs[2][BK][BN];

    const int tid = threadIdx.x;
    const int m0 = blockIdx.y * BM;
    const int n0 = blockIdx.x * BN;

    // Both tiles are [128 rows x 8 K-cols], loaded + transposed identically
    const int t_row = tid >> 1;            // 0..127
    const int t_col = (tid & 1) << 2;      // 0 or 4

    const int tx = tid & 15;
    const int ty = tid >> 4;

    const float scl = *scale_ptr;

    float acc[8][8];
#pragma unroll
    for (int i = 0; i < 8; i++)
#pragma unroll
        for (int j = 0; j < 8; j++) acc[i][j] = 0.0f;

    const float* Aptr = A + (long long)(m0 + t_row) * K + t_col;
    const float* Bptr = B + (long long)(n0 + t_row) * K + t_col;

    float4 areg = *(const float4*)Aptr;
    float4 breg = *(const float4*)Bptr;

    As[0][t_col + 0][t_row] = areg.x;
    As[0][t_col + 1][t_row] = areg.y;
    As[0][t_col + 2][t_row] = areg.z;
    As[0][t_col + 3][t_row] = areg.w;
    Bs[0][t_col + 0][t_row] = breg.x;
    Bs[0][t_col + 1][t_row] = breg.y;
    Bs[0][t_col + 2][t_row] = breg.z;
    Bs[0][t_col + 3][t_row] = breg.w;
    __syncthreads();

    const int ntiles = K / BK;
    for (int t = 0; t < ntiles; t++) {
        const int buf = t & 1;
        if (t + 1 < ntiles) {
            areg = *(const float4*)(Aptr + (t + 1) * BK);
            breg = *(const float4*)(Bptr + (t + 1) * BK);
        }
        float ra[8], rb[8];
#pragma unroll
        for (int k = 0; k < BK; k++) {
            *(float4*)&ra[0] = *(const float4*)&As[buf][k][ty * 4];
            *(float4*)&ra[4] = *(const float4*)&As[buf][k][64 + ty * 4];
            *(float4*)&rb[0] = *(const float4*)&Bs[buf][k][tx * 4];
            *(float4*)&rb[4] = *(const float4*)&Bs[buf][k][64 + tx * 4];
#pragma unroll
            for (int i = 0; i < 8; i++)
#pragma unroll
                for (int j = 0; j < 8; j++)
                    acc[i][j] = fmaf(ra[i], rb[j], acc[i][j]);
        }
        if (t + 1 < ntiles) {
            const int nb = buf ^ 1;
            As[nb][t_col + 0][t_row] = areg.x;
            As[nb][t_col + 1][t_row] = areg.y;
            As[nb][t_col + 2][t_row] = areg.z;
            As[nb][t_col + 3][t_row] = areg.w;
            Bs[nb][t_col + 0][t_row] = breg.x;
            Bs[nb][t_col + 1][t_row] = breg.y;
            Bs[nb][t_col + 2][t_row] = breg.z;
            Bs[nb][t_col + 3][t_row] = breg.w;
            __syncthreads();
        }
    }

#pragma unroll
    for (int ih = 0; ih < 2; ih++)
#pragma unroll
        for (int ii = 0; ii < 4; ii++) {
            const int row = m0 + ih * 64 + ty * 4 + ii;
#pragma unroll
            for (int jh = 0; jh < 2; jh++) {
                const int col = n0 + jh * 64 + tx * 4;
                float4 v;
                v.x = acc[ih * 4 + ii][jh * 4 + 0] * scl;
                v.y = acc[ih * 4 + ii][jh * 4 + 1] * scl;
                v.z = acc[ih * 4 + ii][jh * 4 + 2] * scl;
                v.w = acc[ih * 4 + ii][jh * 4 + 3] * scl;
                *(float4*)(C + (long long)row * N + col) = v;
            }
        }
}

// ---------------------------------------------------------------------------
// Row softmax in-place: one block (256 threads) per row of 2048 elements.
// ---------------------------------------------------------------------------
__global__ __launch_bounds__(256)
void softmax_rows_kernel(float* __restrict__ W)
{
    float* row = W + (long long)blockIdx.x * SS;
    __shared__ float red[256];
    const int tid = threadIdx.x;

    float vals[SS / 256];
    float mx = -INFINITY;
#pragma unroll
    for (int i = 0; i < SS / 256; i++) {
        vals[i] = row[tid + i * 256];
        mx = fmaxf(mx, vals[i]);
    }
    red[tid] = mx;
    __syncthreads();
    for (int s = 128; s > 0; s >>= 1) {
        if (tid < s) red[tid] = fmaxf(red[tid], red[tid + s]);
        __syncthreads();
    }
    mx = red[0];
    __syncthreads();

    float sum = 0.0f;
#pragma unroll
    for (int i = 0; i < SS / 256; i++) {
        vals[i] = expf(vals[i] - mx);
        sum += vals[i];
    }
    red[tid] = sum;
    __syncthreads();
    for (int s = 128; s > 0; s >>= 1) {
        if (tid < s) red[tid] += red[tid + s];
        __syncthreads();
    }
    const float inv = 1.0f / red[0];
#pragma unroll
    for (int i = 0; i < SS / 256; i++)
        row[tid + i * 256] = vals[i] * inv;
}

// ---------------------------------------------------------------------------
// kernel_launch: inputs (metadata order): inputs, Wq, Wk, Wv, Wo, bo, scale
// Output layout: [output (B*S*D)] [weights (B*S*S)]
// ---------------------------------------------------------------------------
extern "C" void kernel_launch(void* const* d_in, const int* in_sizes, int n_in,
                              void* d_out, int out_size)
{
    (void)in_sizes; (void)n_in; (void)out_size;
    const float* X     = (const float*)d_in[0];
    const float* Wq    = (const float*)d_in[1];
    const float* Wk    = (const float*)d_in[2];
    const float* Wv    = (const float*)d_in[3];
    const float* Wo    = (const float*)d_in[4];
    const float* bo    = (const float*)d_in[5];
    const float* scale = (const float*)d_in[6];

    float* out = (float*)d_out;                         // [B,S,D]
    float* wts = out + (long long)BB * SS * DD;         // [B,S,S]

    float *q, *k, *v, *c;
    cudaGetSymbolAddress((void**)&q, g_q);
    cudaGetSymbolAddress((void**)&k, g_k);
    cudaGetSymbolAddress((void**)&v, g_v);
    cudaGetSymbolAddress((void**)&c, g_c);

    const dim3 blk(256);

    // 1) Q/K/V projections: [B*S, D] @ [D, U]
    const dim3 g_qkv(UU / BN, (BB * SS) / BM, 1);
    gemm_nn_kernel<<<g_qkv, blk>>>(X, Wq, q, nullptr, BB * SS, UU, DD, 0, 0, 0);
    gemm_nn_kernel<<<g_qkv, blk>>>(X, Wk, k, nullptr, BB * SS, UU, DD, 0, 0, 0);
    gemm_nn_kernel<<<g_qkv, blk>>>(X, Wv, v, nullptr, BB * SS, UU, DD, 0, 0, 0);

    // 2) scores = (Q @ K^T) * scale, per batch -> weights buffer
    const dim3 g_sc(SS / BN, SS / BM, BB);
    gemm_nt_scaled_kernel<<<g_sc, blk>>>(q, k, wts, scale, SS, SS, UU,
                                         (long long)SS * UU, (long long)SS * UU,
                                         (long long)SS * SS);

    // 3) softmax rows in-place (weights output)
    softmax_rows_kernel<<<BB * SS, 256>>>(wts);

    // 4) context = weights @ V, per batch
    const dim3 g_ctx(UU / BN, SS / BM, BB);
    gemm_nn_kernel<<<g_ctx, blk>>>(wts, v, c, nullptr, SS, UU, SS,
                                   (long long)SS * SS, (long long)SS * UU,
                                   (long long)SS * UU);

    // 5) output = context @ Wo + bo
    const dim3 g_out(DD / BN, (BB * SS) / BM, 1);
    gemm_nn_kernel<<<g_out, blk>>>(c, Wo, out, bo, BB * SS, DD, UU, 0, 0, 0);
}

// round 10
// speedup vs baseline: 2.1116x; 2.1116x over previous
#include <cuda_runtime.h>
#include <cuda_bf16.h>
#include <math.h>
#include <stdint.h>

// ---------------------------------------------------------------------------
// Problem constants
// ---------------------------------------------------------------------------
#define BB 4
#define SS 2048
#define DD 1024
#define UU 1024

typedef __nv_bfloat16 bf16;

// GEMM tiling
#define BM 128
#define BN 128
#define KC 64                       // bf16 K elems per chunk (128B rows)
#define STAGES 3
#define TILE_BYTES (128 * 128)      // one 128x64 bf16 tile = 16 KB
#define STAGE_BYTES (4 * TILE_BYTES)
#define GEMM_SMEM (STAGES * STAGE_BYTES)   // 192 KB

// ---------------------------------------------------------------------------
// Scratch (device globals; allocations are forbidden)
// ---------------------------------------------------------------------------
static __device__ bf16  g_xb [(size_t)BB * SS * DD];
static __device__ bf16  g_xs [(size_t)BB * SS * DD];
static __device__ bf16  g_qb [(size_t)BB * SS * UU];
static __device__ bf16  g_qs [(size_t)BB * SS * UU];
static __device__ bf16  g_kb [(size_t)BB * SS * UU];
static __device__ bf16  g_ks [(size_t)BB * SS * UU];
static __device__ float g_v  [(size_t)BB * SS * UU];
static __device__ bf16  g_vtb[(size_t)BB * SS * UU];
static __device__ bf16  g_vts[(size_t)BB * SS * UU];
static __device__ bf16  g_pb [(size_t)BB * SS * SS];
static __device__ bf16  g_ps [(size_t)BB * SS * SS];
static __device__ bf16  g_cb [(size_t)BB * SS * UU];
static __device__ bf16  g_cs [(size_t)BB * SS * UU];
static __device__ bf16  g_wqb[(size_t)DD * UU];
static __device__ bf16  g_wqs[(size_t)DD * UU];
static __device__ bf16  g_wkb[(size_t)DD * UU];
static __device__ bf16  g_wks[(size_t)DD * UU];
static __device__ bf16  g_wvb[(size_t)DD * UU];
static __device__ bf16  g_wvs[(size_t)DD * UU];
static __device__ bf16  g_wob[(size_t)DD * UU];
static __device__ bf16  g_wos[(size_t)DD * UU];

// ---------------------------------------------------------------------------
// Base-ISA PTX helpers (no sm_103a-only features!)
// ---------------------------------------------------------------------------
__device__ __forceinline__ uint32_t smem_u32_of(const void* p) {
    uint32_t a;
    asm("{ .reg .u64 t; cvta.to.shared.u64 t, %1; cvt.u32.u64 %0, t; }"
        : "=r"(a) : "l"(p));
    return a;
}

__device__ __forceinline__ void cp16(uint32_t dst, const void* src) {
    asm volatile("cp.async.cg.shared.global [%0], [%1], 16;"
                 :: "r"(dst), "l"(src) : "memory");
}
__device__ __forceinline__ void cp_commit() {
    asm volatile("cp.async.commit_group;" ::: "memory");
}
template <int N>
__device__ __forceinline__ void cp_wait() {
    asm volatile("cp.async.wait_group %0;" :: "n"(N) : "memory");
}

__device__ __forceinline__ void ldsm4(uint32_t* r, uint32_t addr) {
    asm volatile("ldmatrix.sync.aligned.m8n8.x4.shared.b16 {%0,%1,%2,%3}, [%4];"
                 : "=r"(r[0]), "=r"(r[1]), "=r"(r[2]), "=r"(r[3]) : "r"(addr));
}

__device__ __forceinline__ void mma16816(float* d, const uint32_t* a,
                                         uint32_t b0, uint32_t b1) {
    asm volatile(
        "mma.sync.aligned.m16n8k16.row.col.f32.bf16.bf16.f32 "
        "{%0,%1,%2,%3}, {%4,%5,%6,%7}, {%8,%9}, {%0,%1,%2,%3};"
        : "+f"(d[0]), "+f"(d[1]), "+f"(d[2]), "+f"(d[3])
        : "r"(a[0]), "r"(a[1]), "r"(a[2]), "r"(a[3]), "r"(b0), "r"(b1));
}

// Split a pair of fp32 into packed bf16 big + bf16 small (residual)
__device__ __forceinline__ void split_pair(float x, float y,
                                           uint32_t& big, uint32_t& sml) {
    __nv_bfloat162 b = __floats2bfloat162_rn(x, y);
    float bx = __bfloat162float(b.x), by = __bfloat162float(b.y);
    __nv_bfloat162 s = __floats2bfloat162_rn(x - bx, y - by);
    big = *reinterpret_cast<uint32_t*>(&b);
    sml = *reinterpret_cast<uint32_t*>(&s);
}

// ---------------------------------------------------------------------------
// NT GEMM, bf16x3 fp32 emulation:
//   C[M,N] = (Ab+As)[M,K] * (Bb+Bs)[N,K]^T  (3 terms, AsBs dropped)
// Optional fp32 C (scaled, biased) and/or bf16 big/small split outputs.
// A/B operands are pre-split bf16, K-major. M,N % 128 == 0, K % 64 == 0.
// Batched via blockIdx.z (element strides).
// ---------------------------------------------------------------------------
__global__ void __launch_bounds__(256) gemm_bf16x3_kernel(
    const bf16* __restrict__ Ab, const bf16* __restrict__ As,
    const bf16* __restrict__ Bb, const bf16* __restrict__ Bs,
    float* __restrict__ C, bf16* __restrict__ Ob, bf16* __restrict__ Os,
    const float* __restrict__ scale_ptr, const float* __restrict__ bias,
    int M, int N, int K,
    long long strA, long long strB, long long strC)
{
    extern __shared__ char smem[];
    const int t  = threadIdx.x;
    const int m0 = blockIdx.y * BM;
    const int n0 = blockIdx.x * BN;
    const long long z = blockIdx.z;

    const char* pAb = (const char*)(Ab + z * strA);
    const char* pAs = (const char*)(As + z * strA);
    const char* pBb = (const char*)(Bb + z * strB);
    const char* pBs = (const char*)(Bs + z * strB);

    const uint32_t sbase = smem_u32_of(smem);
    const int nch = K / KC;
    const size_t ldb = (size_t)K * 2;     // row stride in bytes (A and B)

    // producer: 16 cp.async per thread per chunk; coalesced 128B rows,
    // XOR-swizzled smem (row*128 + ((kg ^ (row&7))<<4))
    const int prow = t >> 3;              // 0..31
    const int pkg  = t & 7;               // 0..7

#define PRODUCE(ch, st)                                                        \
    do {                                                                       \
        uint32_t s0 = sbase + (st) * STAGE_BYTES;                              \
        size_t colb = (size_t)(ch) * 128 + pkg * 16;                          \
        _Pragma("unroll")                                                      \
        for (int i = 0; i < 4; i++) {                                          \
            int row = i * 32 + prow;                                           \
            uint32_t so = (uint32_t)(row * 128 + ((pkg ^ (row & 7)) << 4));    \
            size_t ga = (size_t)(m0 + row) * ldb + colb;                       \
            size_t gb = (size_t)(n0 + row) * ldb + colb;                       \
            cp16(s0 + so,                  pAb + ga);                          \
            cp16(s0 + TILE_BYTES + so,     pAs + ga);                          \
            cp16(s0 + 2 * TILE_BYTES + so, pBb + gb);                          \
            cp16(s0 + 3 * TILE_BYTES + so, pBs + gb);                          \
        }                                                                      \
        cp_commit();                                                           \
    } while (0)

    PRODUCE(0, 0);
    if (nch > 1) PRODUCE(1, 1);

    // consumer layout: 8 warps = 2(M) x 4(N); warp tile 64x32
    const int lane = t & 31;
    const int wid  = t >> 5;
    const int wm   = (wid >> 2) * 64;
    const int wn   = (wid & 3) * 32;
    const int lrow = lane & 15;
    const int lkg  = lane >> 4;

    float acc[4][4][4];
#pragma unroll
    for (int i = 0; i < 4; i++)
#pragma unroll
        for (int j = 0; j < 4; j++)
#pragma unroll
            for (int r = 0; r < 4; r++) acc[i][j][r] = 0.0f;

    for (int ch = 0; ch < nch; ch++) {
        if (ch + 2 < nch) { PRODUCE(ch + 2, (ch + 2) % STAGES); cp_wait<2>(); }
        else if (ch + 1 < nch) { cp_wait<1>(); }
        else { cp_wait<0>(); }
        __syncthreads();

        const uint32_t st = sbase + (ch % STAGES) * STAGE_BYTES;

#pragma unroll
        for (int ks = 0; ks < 4; ks++) {
            const int kg = ks * 2 + lkg;
            uint32_t a_b[4][4], a_s[4][4], b_b[2][4], b_s[2][4];
#pragma unroll
            for (int mt = 0; mt < 4; mt++) {
                int r = wm + mt * 16 + lrow;
                uint32_t off = (uint32_t)(r * 128 + ((kg ^ (r & 7)) << 4));
                ldsm4(a_b[mt], st + off);
                ldsm4(a_s[mt], st + TILE_BYTES + off);
            }
#pragma unroll
            for (int nt = 0; nt < 2; nt++) {
                int r = wn + nt * 16 + lrow;
                uint32_t off = (uint32_t)(r * 128 + ((kg ^ (r & 7)) << 4));
                ldsm4(b_b[nt], st + 2 * TILE_BYTES + off);
                ldsm4(b_s[nt], st + 3 * TILE_BYTES + off);
            }
#pragma unroll
            for (int mt = 0; mt < 4; mt++)
#pragma unroll
                for (int nt = 0; nt < 4; nt++) {
                    const uint32_t bb0 = b_b[nt >> 1][nt & 1];
                    const uint32_t bb1 = b_b[nt >> 1][(nt & 1) + 2];
                    const uint32_t bs0 = b_s[nt >> 1][nt & 1];
                    const uint32_t bs1 = b_s[nt >> 1][(nt & 1) + 2];
                    mma16816(acc[mt][nt], a_b[mt], bb0, bb1);   // big*big
                    mma16816(acc[mt][nt], a_b[mt], bs0, bs1);   // big*small
                    mma16816(acc[mt][nt], a_s[mt], bb0, bb1);   // small*big
                }
        }
        __syncthreads();
    }
#undef PRODUCE

    // epilogue: c-frag lane l: (m = l/4 [+8], n = 2*(l%4)+{0,1})
    const float scl = scale_ptr ? *scale_ptr : 1.0f;
    float* pC  = C  ? C  + z * strC : nullptr;
    bf16*  pOb = Ob ? Ob + z * strC : nullptr;
    bf16*  pOs = Os ? Os + z * strC : nullptr;
    const int l4 = lane >> 2;
    const int lc = (lane & 3) * 2;

#pragma unroll
    for (int mt = 0; mt < 4; mt++)
#pragma unroll
        for (int nt = 0; nt < 4; nt++) {
            const int r0  = m0 + wm + mt * 16 + l4;
            const int r1  = r0 + 8;
            const int col = n0 + wn + nt * 8 + lc;
            float v0 = acc[mt][nt][0] * scl;
            float v1 = acc[mt][nt][1] * scl;
            float v2 = acc[mt][nt][2] * scl;
            float v3 = acc[mt][nt][3] * scl;
            if (bias) {
                const float b0 = bias[col], b1 = bias[col + 1];
                v0 += b0; v1 += b1; v2 += b0; v3 += b1;
            }
            if (pC) {
                *(float2*)(pC + (long long)r0 * N + col) = make_float2(v0, v1);
                *(float2*)(pC + (long long)r1 * N + col) = make_float2(v2, v3);
            }
            if (pOb) {
                uint32_t bg, sm;
                split_pair(v0, v1, bg, sm);
                *(uint32_t*)(pOb + (long long)r0 * N + col) = bg;
                *(uint32_t*)(pOs + (long long)r0 * N + col) = sm;
                split_pair(v2, v3, bg, sm);
                *(uint32_t*)(pOb + (long long)r1 * N + col) = bg;
                *(uint32_t*)(pOs + (long long)r1 * N + col) = sm;
            }
        }
}

// ---------------------------------------------------------------------------
// Elementwise fp32 -> bf16 big/small split
// ---------------------------------------------------------------------------
__global__ __launch_bounds__(256) void convert_split_kernel(
    const float* __restrict__ in, bf16* __restrict__ ob, bf16* __restrict__ os)
{
    const long long i = (long long)blockIdx.x * 256 + threadIdx.x; // float4 idx
    float4 v = ((const float4*)in)[i];
    uint32_t b0, s0, b1, s1;
    split_pair(v.x, v.y, b0, s0);
    split_pair(v.z, v.w, b1, s1);
    ((uint2*)ob)[i] = make_uint2(b0, b1);
    ((uint2*)os)[i] = make_uint2(s0, s1);
}

// ---------------------------------------------------------------------------
// Transpose + split: out_{b,s}[n][m] = split(in[m][n]); in is MxN fp32.
// ---------------------------------------------------------------------------
__global__ __launch_bounds__(256) void transpose_split_kernel(
    const float* __restrict__ in, bf16* __restrict__ ob, bf16* __restrict__ os,
    int M, int N, long long sIn, long long sOut)
{
    in += (long long)blockIdx.z * sIn;
    ob += (long long)blockIdx.z * sOut;
    os += (long long)blockIdx.z * sOut;
    __shared__ float t[32][33];
    const int bx = blockIdx.x * 32;   // n
    const int by = blockIdx.y * 32;   // m
    const int x = threadIdx.x, y = threadIdx.y;
#pragma unroll
    for (int i = 0; i < 32; i += 8)
        t[y + i][x] = in[(long long)(by + y + i) * N + bx + x];
    __syncthreads();
#pragma unroll
    for (int i = 0; i < 32; i += 8) {
        float v = t[x][y + i];
        bf16 b = __float2bfloat16(v);
        bf16 s = __float2bfloat16(v - __bfloat162float(b));
        const long long o = (long long)(bx + y + i) * M + by + x;
        ob[o] = b;
        os[o] = s;
    }
}

// ---------------------------------------------------------------------------
// Row softmax in-place (fp32) + bf16 big/small split outputs.
// One block per row of 2048; each thread owns 8 consecutive elements.
// ---------------------------------------------------------------------------
__global__ __launch_bounds__(256) void softmax_split_kernel(
    float* __restrict__ W, bf16* __restrict__ Pb, bf16* __restrict__ Ps)
{
    const long long base = (long long)blockIdx.x * SS;
    float* row = W + base;
    const int t = threadIdx.x;
    __shared__ float red[256];

    float4 a = *(float4*)(row + t * 8);
    float4 b = *(float4*)(row + t * 8 + 4);

    float mx = fmaxf(fmaxf(fmaxf(a.x, a.y), fmaxf(a.z, a.w)),
                     fmaxf(fmaxf(b.x, b.y), fmaxf(b.z, b.w)));
    red[t] = mx;
    __syncthreads();
    for (int s = 128; s > 0; s >>= 1) {
        if (t < s) red[t] = fmaxf(red[t], red[t + s]);
        __syncthreads();
    }
    mx = red[0];
    __syncthreads();

    a.x = expf(a.x - mx); a.y = expf(a.y - mx);
    a.z = expf(a.z - mx); a.w = expf(a.w - mx);
    b.x = expf(b.x - mx); b.y = expf(b.y - mx);
    b.z = expf(b.z - mx); b.w = expf(b.w - mx);
    float sum = a.x + a.y + a.z + a.w + b.x + b.y + b.z + b.w;
    red[t] = sum;
    __syncthreads();
    for (int s = 128; s > 0; s >>= 1) {
        if (t < s) red[t] += red[t + s];
        __syncthreads();
    }
    const float inv = 1.0f / red[0];
    a.x *= inv; a.y *= inv; a.z *= inv; a.w *= inv;
    b.x *= inv; b.y *= inv; b.z *= inv; b.w *= inv;

    *(float4*)(row + t * 8)     = a;
    *(float4*)(row + t * 8 + 4) = b;

    uint32_t bg[4], sm[4];
    split_pair(a.x, a.y, bg[0], sm[0]);
    split_pair(a.z, a.w, bg[1], sm[1]);
    split_pair(b.x, b.y, bg[2], sm[2]);
    split_pair(b.z, b.w, bg[3], sm[3]);
    *(uint4*)((char*)Pb + (base + t * 8) * 2) = make_uint4(bg[0], bg[1], bg[2], bg[3]);
    *(uint4*)((char*)Ps + (base + t * 8) * 2) = make_uint4(sm[0], sm[1], sm[2], sm[3]);
}

// ---------------------------------------------------------------------------
// kernel_launch — inputs: inputs, Wq, Wk, Wv, Wo, bo, scale
// output: [output (B*S*D)] [weights (B*S*S)]
// ---------------------------------------------------------------------------
extern "C" void kernel_launch(void* const* d_in, const int* in_sizes, int n_in,
                              void* d_out, int out_size)
{
    (void)in_sizes; (void)n_in; (void)out_size;
    const float* X     = (const float*)d_in[0];
    const float* Wq    = (const float*)d_in[1];
    const float* Wk    = (const float*)d_in[2];
    const float* Wv    = (const float*)d_in[3];
    const float* Wo    = (const float*)d_in[4];
    const float* bo    = (const float*)d_in[5];
    const float* scale = (const float*)d_in[6];

    float* out = (float*)d_out;                     // [B,S,D]
    float* wts = out + (long long)BB * SS * DD;     // [B,S,S]

    bf16 *xb, *xs, *qb, *qs, *kb, *ks, *vtb, *vts, *pb, *ps, *cb, *cs;
    bf16 *wqb, *wqs, *wkb, *wks, *wvb, *wvs, *wob, *wos;
    float* v;
    cudaGetSymbolAddress((void**)&xb,  g_xb);
    cudaGetSymbolAddress((void**)&xs,  g_xs);
    cudaGetSymbolAddress((void**)&qb,  g_qb);
    cudaGetSymbolAddress((void**)&qs,  g_qs);
    cudaGetSymbolAddress((void**)&kb,  g_kb);
    cudaGetSymbolAddress((void**)&ks,  g_ks);
    cudaGetSymbolAddress((void**)&v,   g_v);
    cudaGetSymbolAddress((void**)&vtb, g_vtb);
    cudaGetSymbolAddress((void**)&vts, g_vts);
    cudaGetSymbolAddress((void**)&pb,  g_pb);
    cudaGetSymbolAddress((void**)&ps,  g_ps);
    cudaGetSymbolAddress((void**)&cb,  g_cb);
    cudaGetSymbolAddress((void**)&cs,  g_cs);
    cudaGetSymbolAddress((void**)&wqb, g_wqb);
    cudaGetSymbolAddress((void**)&wqs, g_wqs);
    cudaGetSymbolAddress((void**)&wkb, g_wkb);
    cudaGetSymbolAddress((void**)&wks, g_wks);
    cudaGetSymbolAddress((void**)&wvb, g_wvb);
    cudaGetSymbolAddress((void**)&wvs, g_wvs);
    cudaGetSymbolAddress((void**)&wob, g_wob);
    cudaGetSymbolAddress((void**)&wos, g_wos);

    cudaFuncSetAttribute(gemm_bf16x3_kernel,
                         cudaFuncAttributeMaxDynamicSharedMemorySize, GEMM_SMEM);

    const dim3 tblk(32, 8);

    // Pre-split inputs: X elementwise; weights transposed to [N,K] K-major
    convert_split_kernel<<<(BB * SS * DD) / (256 * 4), 256>>>(X, xb, xs);
    transpose_split_kernel<<<dim3(32, 32, 1), tblk>>>(Wq, wqb, wqs, DD, UU, 0, 0);
    transpose_split_kernel<<<dim3(32, 32, 1), tblk>>>(Wk, wkb, wks, DD, UU, 0, 0);
    transpose_split_kernel<<<dim3(32, 32, 1), tblk>>>(Wv, wvb, wvs, DD, UU, 0, 0);
    transpose_split_kernel<<<dim3(32, 32, 1), tblk>>>(Wo, wob, wos, UU, DD, 0, 0);

    // 1) Q/K projections -> bf16 splits only; V -> fp32 (needs transpose)
    const dim3 g_qkv(UU / BN, (BB * SS) / BM, 1);
    gemm_bf16x3_kernel<<<g_qkv, 256, GEMM_SMEM>>>(
        xb, xs, wqb, wqs, nullptr, qb, qs, nullptr, nullptr,
        BB * SS, UU, DD, 0, 0, 0);
    gemm_bf16x3_kernel<<<g_qkv, 256, GEMM_SMEM>>>(
        xb, xs, wkb, wks, nullptr, kb, ks, nullptr, nullptr,
        BB * SS, UU, DD, 0, 0, 0);
    gemm_bf16x3_kernel<<<g_qkv, 256, GEMM_SMEM>>>(
        xb, xs, wvb, wvs, v, nullptr, nullptr, nullptr, nullptr,
        BB * SS, UU, DD, 0, 0, 0);

    // 2) scores = (Q @ K^T) * scale -> wts (fp32 output)
    const dim3 g_sc(SS / BN, SS / BM, BB);
    gemm_bf16x3_kernel<<<g_sc, 256, GEMM_SMEM>>>(
        qb, qs, kb, ks, wts, nullptr, nullptr, scale, nullptr,
        SS, SS, UU,
        (long long)SS * UU, (long long)SS * UU, (long long)SS * SS);

    // 3) softmax in place + split probs
    softmax_split_kernel<<<BB * SS, 256>>>(wts, pb, ps);

    // 4) transpose V per batch -> vt splits [U,S]
    transpose_split_kernel<<<dim3(UU / 32, SS / 32, BB), tblk>>>(
        v, vtb, vts, SS, UU, (long long)SS * UU, (long long)SS * UU);

    // 5) context = P @ V -> c splits
    const dim3 g_ctx(UU / BN, SS / BM, BB);
    gemm_bf16x3_kernel<<<g_ctx, 256, GEMM_SMEM>>>(
        pb, ps, vtb, vts, nullptr, cb, cs, nullptr, nullptr,
        SS, UU, SS,
        (long long)SS * SS, (long long)SS * UU, (long long)SS * UU);

    // 6) output = context @ Wo + bo (c is contiguous [B*S, U])
    const dim3 g_out(DD / BN, (BB * SS) / BM, 1);
    gemm_bf16x3_kernel<<<g_out, 256, GEMM_SMEM>>>(
        cb, cs, wob, wos, out, nullptr, nullptr, nullptr, bo,
        BB * SS, DD, UU, 0, 0, 0);
}

// round 11
// speedup vs baseline: 2.1139x; 1.0011x over previous
#include <cuda_runtime.h>
#include <cuda_bf16.h>
#include <math.h>
#include <stdint.h>

// ---------------------------------------------------------------------------
// Problem constants
// ---------------------------------------------------------------------------
#define BB 4
#define SS 2048
#define DD 1024
#define UU 1024

typedef __nv_bfloat16 bf16;

// GEMM tiling
#define BM 128
#define BN 128
#define KC 64                       // bf16 K elems per chunk (128B rows)
#define STAGES 3
#define TILE_BYTES (128 * 128)      // one 128x64 bf16 tile = 16 KB
#define STAGE_BYTES (4 * TILE_BYTES)
#define GEMM_SMEM (STAGES * STAGE_BYTES)   // 192 KB

// ---------------------------------------------------------------------------
// Scratch (device globals; allocations are forbidden)
// ---------------------------------------------------------------------------
static __device__ bf16  g_xb [(size_t)BB * SS * DD];
static __device__ bf16  g_xs [(size_t)BB * SS * DD];
static __device__ bf16  g_qb [(size_t)BB * SS * UU];
static __device__ bf16  g_qs [(size_t)BB * SS * UU];
static __device__ bf16  g_kb [(size_t)BB * SS * UU];
static __device__ bf16  g_ks [(size_t)BB * SS * UU];
static __device__ float g_v  [(size_t)BB * SS * UU];
static __device__ bf16  g_vtb[(size_t)BB * SS * UU];
static __device__ bf16  g_vts[(size_t)BB * SS * UU];
static __device__ bf16  g_pb [(size_t)BB * SS * SS];
static __device__ bf16  g_ps [(size_t)BB * SS * SS];
static __device__ bf16  g_cb [(size_t)BB * SS * UU];
static __device__ bf16  g_cs [(size_t)BB * SS * UU];
static __device__ bf16  g_wqb[(size_t)DD * UU];
static __device__ bf16  g_wqs[(size_t)DD * UU];
static __device__ bf16  g_wkb[(size_t)DD * UU];
static __device__ bf16  g_wks[(size_t)DD * UU];
static __device__ bf16  g_wvb[(size_t)DD * UU];
static __device__ bf16  g_wvs[(size_t)DD * UU];
static __device__ bf16  g_wob[(size_t)DD * UU];
static __device__ bf16  g_wos[(size_t)DD * UU];

// ---------------------------------------------------------------------------
// Base-ISA PTX helpers (no sm_103a-only features!)
// ---------------------------------------------------------------------------
__device__ __forceinline__ uint32_t smem_u32_of(const void* p) {
    uint32_t a;
    asm("{ .reg .u64 t; cvta.to.shared.u64 t, %1; cvt.u32.u64 %0, t; }"
        : "=r"(a) : "l"(p));
    return a;
}

__device__ __forceinline__ void cp16(uint32_t dst, const void* src) {
    asm volatile("cp.async.cg.shared.global [%0], [%1], 16;"
                 :: "r"(dst), "l"(src) : "memory");
}
__device__ __forceinline__ void cp_commit() {
    asm volatile("cp.async.commit_group;" ::: "memory");
}
template <int N>
__device__ __forceinline__ void cp_wait() {
    asm volatile("cp.async.wait_group %0;" :: "n"(N) : "memory");
}

__device__ __forceinline__ void ldsm4(uint32_t* r, uint32_t addr) {
    asm volatile("ldmatrix.sync.aligned.m8n8.x4.shared.b16 {%0,%1,%2,%3}, [%4];"
                 : "=r"(r[0]), "=r"(r[1]), "=r"(r[2]), "=r"(r[3]) : "r"(addr));
}

__device__ __forceinline__ void mma16816(float* d, const uint32_t* a,
                                         uint32_t b0, uint32_t b1) {
    asm volatile(
        "mma.sync.aligned.m16n8k16.row.col.f32.bf16.bf16.f32 "
        "{%0,%1,%2,%3}, {%4,%5,%6,%7}, {%8,%9}, {%0,%1,%2,%3};"
        : "+f"(d[0]), "+f"(d[1]), "+f"(d[2]), "+f"(d[3])
        : "r"(a[0]), "r"(a[1]), "r"(a[2]), "r"(a[3]), "r"(b0), "r"(b1));
}

// Split a pair of fp32 into packed bf16 big + bf16 small (residual)
__device__ __forceinline__ void split_pair(float x, float y,
                                           uint32_t& big, uint32_t& sml) {
    __nv_bfloat162 b = __floats2bfloat162_rn(x, y);
    float bx = __bfloat162float(b.x), by = __bfloat162float(b.y);
    __nv_bfloat162 s = __floats2bfloat162_rn(x - bx, y - by);
    big = *reinterpret_cast<uint32_t*>(&b);
    sml = *reinterpret_cast<uint32_t*>(&s);
}

// ---------------------------------------------------------------------------
// NT GEMM, bf16x3 fp32 emulation:
//   C[M,N] = (Ab+As)[M,K] * (Bb+Bs)[N,K]^T  (3 terms, AsBs dropped)
// Optional fp32 C (scaled, biased) and/or bf16 big/small split outputs.
// A/B operands are pre-split bf16, K-major. M,N % 128 == 0, K % 64 == 0.
// Batched via blockIdx.z (element strides).
// ---------------------------------------------------------------------------
__global__ void __launch_bounds__(256) gemm_bf16x3_kernel(
    const bf16* __restrict__ Ab, const bf16* __restrict__ As,
    const bf16* __restrict__ Bb, const bf16* __restrict__ Bs,
    float* __restrict__ C, bf16* __restrict__ Ob, bf16* __restrict__ Os,
    const float* __restrict__ scale_ptr, const float* __restrict__ bias,
    int M, int N, int K,
    long long strA, long long strB, long long strC)
{
    extern __shared__ char smem[];
    const int t  = threadIdx.x;
    const int m0 = blockIdx.y * BM;
    const int n0 = blockIdx.x * BN;
    const long long z = blockIdx.z;

    const char* pAb = (const char*)(Ab + z * strA);
    const char* pAs = (const char*)(As + z * strA);
    const char* pBb = (const char*)(Bb + z * strB);
    const char* pBs = (const char*)(Bs + z * strB);

    const uint32_t sbase = smem_u32_of(smem);
    const int nch = K / KC;
    const size_t ldb = (size_t)K * 2;     // row stride in bytes (A and B)

    // producer: 16 cp.async per thread per chunk; coalesced 128B rows,
    // XOR-swizzled smem (row*128 + ((kg ^ (row&7))<<4))
    const int prow = t >> 3;              // 0..31
    const int pkg  = t & 7;               // 0..7

#define PRODUCE(ch, st)                                                        \
    do {                                                                       \
        uint32_t s0 = sbase + (st) * STAGE_BYTES;                              \
        size_t colb = (size_t)(ch) * 128 + pkg * 16;                          \
        _Pragma("unroll")                                                      \
        for (int i = 0; i < 4; i++) {                                          \
            int row = i * 32 + prow;                                           \
            uint32_t so = (uint32_t)(row * 128 + ((pkg ^ (row & 7)) << 4));    \
            size_t ga = (size_t)(m0 + row) * ldb + colb;                       \
            size_t gb = (size_t)(n0 + row) * ldb + colb;                       \
            cp16(s0 + so,                  pAb + ga);                          \
            cp16(s0 + TILE_BYTES + so,     pAs + ga);                          \
            cp16(s0 + 2 * TILE_BYTES + so, pBb + gb);                          \
            cp16(s0 + 3 * TILE_BYTES + so, pBs + gb);                          \
        }                                                                      \
        cp_commit();                                                           \
    } while (0)

    PRODUCE(0, 0);
    if (nch > 1) PRODUCE(1, 1);

    // consumer layout: 8 warps = 2(M) x 4(N); warp tile 64x32
    const int lane = t & 31;
    const int wid  = t >> 5;
    const int wm   = (wid >> 2) * 64;
    const int wn   = (wid & 3) * 32;
    const int lrow = lane & 15;
    const int lkg  = lane >> 4;

    float acc[4][4][4];
#pragma unroll
    for (int i = 0; i < 4; i++)
#pragma unroll
        for (int j = 0; j < 4; j++)
#pragma unroll
            for (int r = 0; r < 4; r++) acc[i][j][r] = 0.0f;

    for (int ch = 0; ch < nch; ch++) {
        if (ch + 2 < nch) { PRODUCE(ch + 2, (ch + 2) % STAGES); cp_wait<2>(); }
        else if (ch + 1 < nch) { cp_wait<1>(); }
        else { cp_wait<0>(); }
        __syncthreads();

        const uint32_t st = sbase + (ch % STAGES) * STAGE_BYTES;

#pragma unroll
        for (int ks = 0; ks < 4; ks++) {
            const int kg = ks * 2 + lkg;
            uint32_t a_b[4][4], a_s[4][4], b_b[2][4], b_s[2][4];
#pragma unroll
            for (int mt = 0; mt < 4; mt++) {
                int r = wm + mt * 16 + lrow;
                uint32_t off = (uint32_t)(r * 128 + ((kg ^ (r & 7)) << 4));
                ldsm4(a_b[mt], st + off);
                ldsm4(a_s[mt], st + TILE_BYTES + off);
            }
#pragma unroll
            for (int nt = 0; nt < 2; nt++) {
                int r = wn + nt * 16 + lrow;
                uint32_t off = (uint32_t)(r * 128 + ((kg ^ (r & 7)) << 4));
                ldsm4(b_b[nt], st + 2 * TILE_BYTES + off);
                ldsm4(b_s[nt], st + 3 * TILE_BYTES + off);
            }
#pragma unroll
            for (int mt = 0; mt < 4; mt++)
#pragma unroll
                for (int nt = 0; nt < 4; nt++) {
                    const uint32_t bb0 = b_b[nt >> 1][nt & 1];
                    const uint32_t bb1 = b_b[nt >> 1][(nt & 1) + 2];
                    const uint32_t bs0 = b_s[nt >> 1][nt & 1];
                    const uint32_t bs1 = b_s[nt >> 1][(nt & 1) + 2];
                    mma16816(acc[mt][nt], a_b[mt], bb0, bb1);   // big*big
                    mma16816(acc[mt][nt], a_b[mt], bs0, bs1);   // big*small
                    mma16816(acc[mt][nt], a_s[mt], bb0, bb1);   // small*big
                }
        }
        __syncthreads();
    }
#undef PRODUCE

    // epilogue: c-frag lane l: (m = l/4 [+8], n = 2*(l%4)+{0,1})
    const float scl = scale_ptr ? *scale_ptr : 1.0f;
    float* pC  = C  ? C  + z * strC : nullptr;
    bf16*  pOb = Ob ? Ob + z * strC : nullptr;
    bf16*  pOs = Os ? Os + z * strC : nullptr;
    const int l4 = lane >> 2;
    const int lc = (lane & 3) * 2;

#pragma unroll
    for (int mt = 0; mt < 4; mt++)
#pragma unroll
        for (int nt = 0; nt < 4; nt++) {
            const int r0  = m0 + wm + mt * 16 + l4;
            const int r1  = r0 + 8;
            const int col = n0 + wn + nt * 8 + lc;
            float v0 = acc[mt][nt][0] * scl;
            float v1 = acc[mt][nt][1] * scl;
            float v2 = acc[mt][nt][2] * scl;
            float v3 = acc[mt][nt][3] * scl;
            if (bias) {
                const float b0 = bias[col], b1 = bias[col + 1];
                v0 += b0; v1 += b1; v2 += b0; v3 += b1;
            }
            if (pC) {
                *(float2*)(pC + (long long)r0 * N + col) = make_float2(v0, v1);
                *(float2*)(pC + (long long)r1 * N + col) = make_float2(v2, v3);
            }
            if (pOb) {
                uint32_t bg, sm;
                split_pair(v0, v1, bg, sm);
                *(uint32_t*)(pOb + (long long)r0 * N + col) = bg;
                *(uint32_t*)(pOs + (long long)r0 * N + col) = sm;
                split_pair(v2, v3, bg, sm);
                *(uint32_t*)(pOb + (long long)r1 * N + col) = bg;
                *(uint32_t*)(pOs + (long long)r1 * N + col) = sm;
            }
        }
}

// ---------------------------------------------------------------------------
// Elementwise fp32 -> bf16 big/small split
// ---------------------------------------------------------------------------
__global__ __launch_bounds__(256) void convert_split_kernel(
    const float* __restrict__ in, bf16* __restrict__ ob, bf16* __restrict__ os)
{
    const long long i = (long long)blockIdx.x * 256 + threadIdx.x; // float4 idx
    float4 v = ((const float4*)in)[i];
    uint32_t b0, s0, b1, s1;
    split_pair(v.x, v.y, b0, s0);
    split_pair(v.z, v.w, b1, s1);
    ((uint2*)ob)[i] = make_uint2(b0, b1);
    ((uint2*)os)[i] = make_uint2(s0, s1);
}

// ---------------------------------------------------------------------------
// Transpose + split: out_{b,s}[n][m] = split(in[m][n]); in is MxN fp32.
// ---------------------------------------------------------------------------
__global__ __launch_bounds__(256) void transpose_split_kernel(
    const float* __restrict__ in, bf16* __restrict__ ob, bf16* __restrict__ os,
    int M, int N, long long sIn, long long sOut)
{
    in += (long long)blockIdx.z * sIn;
    ob += (long long)blockIdx.z * sOut;
    os += (long long)blockIdx.z * sOut;
    __shared__ float t[32][33];
    const int bx = blockIdx.x * 32;   // n
    const int by = blockIdx.y * 32;   // m
    const int x = threadIdx.x, y = threadIdx.y;
#pragma unroll
    for (int i = 0; i < 32; i += 8)
        t[y + i][x] = in[(long long)(by + y + i) * N + bx + x];
    __syncthreads();
#pragma unroll
    for (int i = 0; i < 32; i += 8) {
        float v = t[x][y + i];
        bf16 b = __float2bfloat16(v);
        bf16 s = __float2bfloat16(v - __bfloat162float(b));
        const long long o = (long long)(bx + y + i) * M + by + x;
        ob[o] = b;
        os[o] = s;
    }
}

// ---------------------------------------------------------------------------
// Row softmax in-place (fp32) + bf16 big/small split outputs.
// One block per row of 2048; each thread owns 8 consecutive elements.
// ---------------------------------------------------------------------------
__global__ __launch_bounds__(256) void softmax_split_kernel(
    float* __restrict__ W, bf16* __restrict__ Pb, bf16* __restrict__ Ps)
{
    const long long base = (long long)blockIdx.x * SS;
    float* row = W + base;
    const int t = threadIdx.x;
    __shared__ float red[256];

    float4 a = *(float4*)(row + t * 8);
    float4 b = *(float4*)(row + t * 8 + 4);

    float mx = fmaxf(fmaxf(fmaxf(a.x, a.y), fmaxf(a.z, a.w)),
                     fmaxf(fmaxf(b.x, b.y), fmaxf(b.z, b.w)));
    red[t] = mx;
    __syncthreads();
    for (int s = 128; s > 0; s >>= 1) {
        if (t < s) red[t] = fmaxf(red[t], red[t + s]);
        __syncthreads();
    }
    mx = red[0];
    __syncthreads();

    a.x = expf(a.x - mx); a.y = expf(a.y - mx);
    a.z = expf(a.z - mx); a.w = expf(a.w - mx);
    b.x = expf(b.x - mx); b.y = expf(b.y - mx);
    b.z = expf(b.z - mx); b.w = expf(b.w - mx);
    float sum = a.x + a.y + a.z + a.w + b.x + b.y + b.z + b.w;
    red[t] = sum;
    __syncthreads();
    for (int s = 128; s > 0; s >>= 1) {
        if (t < s) red[t] += red[t + s];
        __syncthreads();
    }
    const float inv = 1.0f / red[0];
    a.x *= inv; a.y *= inv; a.z *= inv; a.w *= inv;
    b.x *= inv; b.y *= inv; b.z *= inv; b.w *= inv;

    *(float4*)(row + t * 8)     = a;
    *(float4*)(row + t * 8 + 4) = b;

    uint32_t bg[4], sm[4];
    split_pair(a.x, a.y, bg[0], sm[0]);
    split_pair(a.z, a.w, bg[1], sm[1]);
    split_pair(b.x, b.y, bg[2], sm[2]);
    split_pair(b.z, b.w, bg[3], sm[3]);
    *(uint4*)((char*)Pb + (base + t * 8) * 2) = make_uint4(bg[0], bg[1], bg[2], bg[3]);
    *(uint4*)((char*)Ps + (base + t * 8) * 2) = make_uint4(sm[0], sm[1], sm[2], sm[3]);
}

// ---------------------------------------------------------------------------
// kernel_launch — inputs: inputs, Wq, Wk, Wv, Wo, bo, scale
// output: [output (B*S*D)] [weights (B*S*S)]
// ---------------------------------------------------------------------------
extern "C" void kernel_launch(void* const* d_in, const int* in_sizes, int n_in,
                              void* d_out, int out_size)
{
    (void)in_sizes; (void)n_in; (void)out_size;
    const float* X     = (const float*)d_in[0];
    const float* Wq    = (const float*)d_in[1];
    const float* Wk    = (const float*)d_in[2];
    const float* Wv    = (const float*)d_in[3];
    const float* Wo    = (const float*)d_in[4];
    const float* bo    = (const float*)d_in[5];
    const float* scale = (const float*)d_in[6];

    float* out = (float*)d_out;                     // [B,S,D]
    float* wts = out + (long long)BB * SS * DD;     // [B,S,S]

    bf16 *xb, *xs, *qb, *qs, *kb, *ks, *vtb, *vts, *pb, *ps, *cb, *cs;
    bf16 *wqb, *wqs, *wkb, *wks, *wvb, *wvs, *wob, *wos;
    float* v;
    cudaGetSymbolAddress((void**)&xb,  g_xb);
    cudaGetSymbolAddress((void**)&xs,  g_xs);
    cudaGetSymbolAddress((void**)&qb,  g_qb);
    cudaGetSymbolAddress((void**)&qs,  g_qs);
    cudaGetSymbolAddress((void**)&kb,  g_kb);
    cudaGetSymbolAddress((void**)&ks,  g_ks);
    cudaGetSymbolAddress((void**)&v,   g_v);
    cudaGetSymbolAddress((void**)&vtb, g_vtb);
    cudaGetSymbolAddress((void**)&vts, g_vts);
    cudaGetSymbolAddress((void**)&pb,  g_pb);
    cudaGetSymbolAddress((void**)&ps,  g_ps);
    cudaGetSymbolAddress((void**)&cb,  g_cb);
    cudaGetSymbolAddress((void**)&cs,  g_cs);
    cudaGetSymbolAddress((void**)&wqb, g_wqb);
    cudaGetSymbolAddress((void**)&wqs, g_wqs);
    cudaGetSymbolAddress((void**)&wkb, g_wkb);
    cudaGetSymbolAddress((void**)&wks, g_wks);
    cudaGetSymbolAddress((void**)&wvb, g_wvb);
    cudaGetSymbolAddress((void**)&wvs, g_wvs);
    cudaGetSymbolAddress((void**)&wob, g_wob);
    cudaGetSymbolAddress((void**)&wos, g_wos);

    cudaFuncSetAttribute(gemm_bf16x3_kernel,
                         cudaFuncAttributeMaxDynamicSharedMemorySize, GEMM_SMEM);

    const dim3 tblk(32, 8);

    // Pre-split inputs: X elementwise; weights transposed to [N,K] K-major
    convert_split_kernel<<<(BB * SS * DD) / (256 * 4), 256>>>(X, xb, xs);
    transpose_split_kernel<<<dim3(32, 32, 1), tblk>>>(Wq, wqb, wqs, DD, UU, 0, 0);
    transpose_split_kernel<<<dim3(32, 32, 1), tblk>>>(Wk, wkb, wks, DD, UU, 0, 0);
    transpose_split_kernel<<<dim3(32, 32, 1), tblk>>>(Wv, wvb, wvs, DD, UU, 0, 0);
    transpose_split_kernel<<<dim3(32, 32, 1), tblk>>>(Wo, wob, wos, UU, DD, 0, 0);

    // 1) Q/K projections -> bf16 splits only; V -> fp32 (needs transpose)
    const dim3 g_qkv(UU / BN, (BB * SS) / BM, 1);
    gemm_bf16x3_kernel<<<g_qkv, 256, GEMM_SMEM>>>(
        xb, xs, wqb, wqs, nullptr, qb, qs, nullptr, nullptr,
        BB * SS, UU, DD, 0, 0, 0);
    gemm_bf16x3_kernel<<<g_qkv, 256, GEMM_SMEM>>>(
        xb, xs, wkb, wks, nullptr, kb, ks, nullptr, nullptr,
        BB * SS, UU, DD, 0, 0, 0);
    gemm_bf16x3_kernel<<<g_qkv, 256, GEMM_SMEM>>>(
        xb, xs, wvb, wvs, v, nullptr, nullptr, nullptr, nullptr,
        BB * SS, UU, DD, 0, 0, 0);

    // 2) scores = (Q @ K^T) * scale -> wts (fp32 output)
    const dim3 g_sc(SS / BN, SS / BM, BB);
    gemm_bf16x3_kernel<<<g_sc, 256, GEMM_SMEM>>>(
        qb, qs, kb, ks, wts, nullptr, nullptr, scale, nullptr,
        SS, SS, UU,
        (long long)SS * UU, (long long)SS * UU, (long long)SS * SS);

    // 3) softmax in place + split probs
    softmax_split_kernel<<<BB * SS, 256>>>(wts, pb, ps);

    // 4) transpose V per batch -> vt splits [U,S]
    transpose_split_kernel<<<dim3(UU / 32, SS / 32, BB), tblk>>>(
        v, vtb, vts, SS, UU, (long long)SS * UU, (long long)SS * UU);

    // 5) context = P @ V -> c splits
    const dim3 g_ctx(UU / BN, SS / BM, BB);
    gemm_bf16x3_kernel<<<g_ctx, 256, GEMM_SMEM>>>(
        pb, ps, vtb, vts, nullptr, cb, cs, nullptr, nullptr,
        SS, UU, SS,
        (long long)SS * SS, (long long)SS * UU, (long long)SS * UU);

    // 6) output = context @ Wo + bo (c is contiguous [B*S, U])
    const dim3 g_out(DD / BN, (BB * SS) / BM, 1);
    gemm_bf16x3_kernel<<<g_out, 256, GEMM_SMEM>>>(
        cb, cs, wob, wos, out, nullptr, nullptr, nullptr, bo,
        BB * SS, DD, UU, 0, 0, 0);
}

// round 12
// speedup vs baseline: 2.1147x; 1.0004x over previous
#include <cuda_runtime.h>
#include <cuda_bf16.h>
#include <math.h>
#include <stdint.h>

// ---------------------------------------------------------------------------
// Problem constants
// ---------------------------------------------------------------------------
#define BB 4
#define SS 2048
#define DD 1024
#define UU 1024

typedef __nv_bfloat16 bf16;

// GEMM tiling
#define BM 128
#define BN 128
#define KC 64                       // bf16 K elems per chunk (128B rows)
#define STAGES 3
#define TILE_BYTES (128 * 128)      // one 128x64 bf16 tile = 16 KB
#define STAGE_BYTES (4 * TILE_BYTES)
#define GEMM_SMEM (STAGES * STAGE_BYTES)   // 192 KB

// ---------------------------------------------------------------------------
// Scratch (device globals; allocations are forbidden)
// ---------------------------------------------------------------------------
static __device__ bf16  g_xb [(size_t)BB * SS * DD];
static __device__ bf16  g_xs [(size_t)BB * SS * DD];
static __device__ bf16  g_qb [(size_t)BB * SS * UU];
static __device__ bf16  g_qs [(size_t)BB * SS * UU];
static __device__ bf16  g_kb [(size_t)BB * SS * UU];
static __device__ bf16  g_ks [(size_t)BB * SS * UU];
static __device__ float g_v  [(size_t)BB * SS * UU];
static __device__ bf16  g_vtb[(size_t)BB * SS * UU];
static __device__ bf16  g_vts[(size_t)BB * SS * UU];
static __device__ bf16  g_pb [(size_t)BB * SS * SS];
static __device__ bf16  g_ps [(size_t)BB * SS * SS];
static __device__ bf16  g_cb [(size_t)BB * SS * UU];
static __device__ bf16  g_cs [(size_t)BB * SS * UU];
static __device__ bf16  g_wqb[(size_t)DD * UU];
static __device__ bf16  g_wqs[(size_t)DD * UU];
static __device__ bf16  g_wkb[(size_t)DD * UU];
static __device__ bf16  g_wks[(size_t)DD * UU];
static __device__ bf16  g_wvb[(size_t)DD * UU];
static __device__ bf16  g_wvs[(size_t)DD * UU];
static __device__ bf16  g_wob[(size_t)DD * UU];
static __device__ bf16  g_wos[(size_t)DD * UU];

// ---------------------------------------------------------------------------
// Base-ISA PTX helpers (no sm_103a-only features!)
// ---------------------------------------------------------------------------
__device__ __forceinline__ uint32_t smem_u32_of(const void* p) {
    uint32_t a;
    asm("{ .reg .u64 t; cvta.to.shared.u64 t, %1; cvt.u32.u64 %0, t; }"
        : "=r"(a) : "l"(p));
    return a;
}

__device__ __forceinline__ void cp16(uint32_t dst, const void* src) {
    asm volatile("cp.async.cg.shared.global [%0], [%1], 16;"
                 :: "r"(dst), "l"(src) : "memory");
}
__device__ __forceinline__ void cp_commit() {
    asm volatile("cp.async.commit_group;" ::: "memory");
}
template <int N>
__device__ __forceinline__ void cp_wait() {
    asm volatile("cp.async.wait_group %0;" :: "n"(N) : "memory");
}

__device__ __forceinline__ void ldsm4(uint32_t* r, uint32_t addr) {
    asm volatile("ldmatrix.sync.aligned.m8n8.x4.shared.b16 {%0,%1,%2,%3}, [%4];"
                 : "=r"(r[0]), "=r"(r[1]), "=r"(r[2]), "=r"(r[3]) : "r"(addr));
}

__device__ __forceinline__ void mma16816(float* d, const uint32_t* a,
                                         uint32_t b0, uint32_t b1) {
    asm volatile(
        "mma.sync.aligned.m16n8k16.row.col.f32.bf16.bf16.f32 "
        "{%0,%1,%2,%3}, {%4,%5,%6,%7}, {%8,%9}, {%0,%1,%2,%3};"
        : "+f"(d[0]), "+f"(d[1]), "+f"(d[2]), "+f"(d[3])
        : "r"(a[0]), "r"(a[1]), "r"(a[2]), "r"(a[3]), "r"(b0), "r"(b1));
}

// Split a pair of fp32 into packed bf16 big + bf16 small (residual)
__device__ __forceinline__ void split_pair(float x, float y,
                                           uint32_t& big, uint32_t& sml) {
    __nv_bfloat162 b = __floats2bfloat162_rn(x, y);
    float bx = __bfloat162float(b.x), by = __bfloat162float(b.y);
    __nv_bfloat162 s = __floats2bfloat162_rn(x - bx, y - by);
    big = *reinterpret_cast<uint32_t*>(&b);
    sml = *reinterpret_cast<uint32_t*>(&s);
}

// ---------------------------------------------------------------------------
// NT GEMM, bf16x3 fp32 emulation:
//   C[M,N] = (Ab+As)[M,K] * (Bb+Bs)[N,K]^T  (3 terms, AsBs dropped)
// Optional fp32 C (scaled, biased) and/or bf16 big/small split outputs.
// A/B operands are pre-split bf16, K-major. M,N % 128 == 0, K % 64 == 0.
// Batched via blockIdx.z (element strides).
// ---------------------------------------------------------------------------
__global__ void __launch_bounds__(256) gemm_bf16x3_kernel(
    const bf16* __restrict__ Ab, const bf16* __restrict__ As,
    const bf16* __restrict__ Bb, const bf16* __restrict__ Bs,
    float* __restrict__ C, bf16* __restrict__ Ob, bf16* __restrict__ Os,
    const float* __restrict__ scale_ptr, const float* __restrict__ bias,
    int M, int N, int K,
    long long strA, long long strB, long long strC)
{
    extern __shared__ char smem[];
    const int t  = threadIdx.x;
    const int m0 = blockIdx.y * BM;
    const int n0 = blockIdx.x * BN;
    const long long z = blockIdx.z;

    const char* pAb = (const char*)(Ab + z * strA);
    const char* pAs = (const char*)(As + z * strA);
    const char* pBb = (const char*)(Bb + z * strB);
    const char* pBs = (const char*)(Bs + z * strB);

    const uint32_t sbase = smem_u32_of(smem);
    const int nch = K / KC;
    const size_t ldb = (size_t)K * 2;     // row stride in bytes (A and B)

    // producer: 16 cp.async per thread per chunk; coalesced 128B rows,
    // XOR-swizzled smem (row*128 + ((kg ^ (row&7))<<4))
    const int prow = t >> 3;              // 0..31
    const int pkg  = t & 7;               // 0..7

#define PRODUCE(ch, st)                                                        \
    do {                                                                       \
        uint32_t s0 = sbase + (st) * STAGE_BYTES;                              \
        size_t colb = (size_t)(ch) * 128 + pkg * 16;                          \
        _Pragma("unroll")                                                      \
        for (int i = 0; i < 4; i++) {                                          \
            int row = i * 32 + prow;                                           \
            uint32_t so = (uint32_t)(row * 128 + ((pkg ^ (row & 7)) << 4));    \
            size_t ga = (size_t)(m0 + row) * ldb + colb;                       \
            size_t gb = (size_t)(n0 + row) * ldb + colb;                       \
            cp16(s0 + so,                  pAb + ga);                          \
            cp16(s0 + TILE_BYTES + so,     pAs + ga);                          \
            cp16(s0 + 2 * TILE_BYTES + so, pBb + gb);                          \
            cp16(s0 + 3 * TILE_BYTES + so, pBs + gb);                          \
        }                                                                      \
        cp_commit();                                                           \
    } while (0)

    PRODUCE(0, 0);
    if (nch > 1) PRODUCE(1, 1);

    // consumer layout: 8 warps = 2(M) x 4(N); warp tile 64x32
    const int lane = t & 31;
    const int wid  = t >> 5;
    const int wm   = (wid >> 2) * 64;
    const int wn   = (wid & 3) * 32;
    const int lrow = lane & 15;
    const int lkg  = lane >> 4;

    float acc[4][4][4];
#pragma unroll
    for (int i = 0; i < 4; i++)
#pragma unroll
        for (int j = 0; j < 4; j++)
#pragma unroll
            for (int r = 0; r < 4; r++) acc[i][j][r] = 0.0f;

    for (int ch = 0; ch < nch; ch++) {
        if (ch + 2 < nch) { PRODUCE(ch + 2, (ch + 2) % STAGES); cp_wait<2>(); }
        else if (ch + 1 < nch) { cp_wait<1>(); }
        else { cp_wait<0>(); }
        __syncthreads();

        const uint32_t st = sbase + (ch % STAGES) * STAGE_BYTES;

#pragma unroll
        for (int ks = 0; ks < 4; ks++) {
            const int kg = ks * 2 + lkg;
            uint32_t a_b[4][4], a_s[4][4], b_b[2][4], b_s[2][4];
#pragma unroll
            for (int mt = 0; mt < 4; mt++) {
                int r = wm + mt * 16 + lrow;
                uint32_t off = (uint32_t)(r * 128 + ((kg ^ (r & 7)) << 4));
                ldsm4(a_b[mt], st + off);
                ldsm4(a_s[mt], st + TILE_BYTES + off);
            }
#pragma unroll
            for (int nt = 0; nt < 2; nt++) {
                int r = wn + nt * 16 + lrow;
                uint32_t off = (uint32_t)(r * 128 + ((kg ^ (r & 7)) << 4));
                ldsm4(b_b[nt], st + 2 * TILE_BYTES + off);
                ldsm4(b_s[nt], st + 3 * TILE_BYTES + off);
            }
#pragma unroll
            for (int mt = 0; mt < 4; mt++)
#pragma unroll
                for (int nt = 0; nt < 4; nt++) {
                    const uint32_t bb0 = b_b[nt >> 1][nt & 1];
                    const uint32_t bb1 = b_b[nt >> 1][(nt & 1) + 2];
                    const uint32_t bs0 = b_s[nt >> 1][nt & 1];
                    const uint32_t bs1 = b_s[nt >> 1][(nt & 1) + 2];
                    mma16816(acc[mt][nt], a_b[mt], bb0, bb1);   // big*big
                    mma16816(acc[mt][nt], a_b[mt], bs0, bs1);   // big*small
                    mma16816(acc[mt][nt], a_s[mt], bb0, bb1);   // small*big
                }
        }
        __syncthreads();
    }
#undef PRODUCE

    // epilogue: c-frag lane l: (m = l/4 [+8], n = 2*(l%4)+{0,1})
    const float scl = scale_ptr ? *scale_ptr : 1.0f;
    float* pC  = C  ? C  + z * strC : nullptr;
    bf16*  pOb = Ob ? Ob + z * strC : nullptr;
    bf16*  pOs = Os ? Os + z * strC : nullptr;
    const int l4 = lane >> 2;
    const int lc = (lane & 3) * 2;

#pragma unroll
    for (int mt = 0; mt < 4; mt++)
#pragma unroll
        for (int nt = 0; nt < 4; nt++) {
            const int r0  = m0 + wm + mt * 16 + l4;
            const int r1  = r0 + 8;
            const int col = n0 + wn + nt * 8 + lc;
            float v0 = acc[mt][nt][0] * scl;
            float v1 = acc[mt][nt][1] * scl;
            float v2 = acc[mt][nt][2] * scl;
            float v3 = acc[mt][nt][3] * scl;
            if (bias) {
                const float b0 = bias[col], b1 = bias[col + 1];
                v0 += b0; v1 += b1; v2 += b0; v3 += b1;
            }
            if (pC) {
                *(float2*)(pC + (long long)r0 * N + col) = make_float2(v0, v1);
                *(float2*)(pC + (long long)r1 * N + col) = make_float2(v2, v3);
            }
            if (pOb) {
                uint32_t bg, sm;
                split_pair(v0, v1, bg, sm);
                *(uint32_t*)(pOb + (long long)r0 * N + col) = bg;
                *(uint32_t*)(pOs + (long long)r0 * N + col) = sm;
                split_pair(v2, v3, bg, sm);
                *(uint32_t*)(pOb + (long long)r1 * N + col) = bg;
                *(uint32_t*)(pOs + (long long)r1 * N + col) = sm;
            }
        }
}

// ---------------------------------------------------------------------------
// Elementwise fp32 -> bf16 big/small split
// ---------------------------------------------------------------------------
__global__ __launch_bounds__(256) void convert_split_kernel(
    const float* __restrict__ in, bf16* __restrict__ ob, bf16* __restrict__ os)
{
    const long long i = (long long)blockIdx.x * 256 + threadIdx.x; // float4 idx
    float4 v = ((const float4*)in)[i];
    uint32_t b0, s0, b1, s1;
    split_pair(v.x, v.y, b0, s0);
    split_pair(v.z, v.w, b1, s1);
    ((uint2*)ob)[i] = make_uint2(b0, b1);
    ((uint2*)os)[i] = make_uint2(s0, s1);
}

// ---------------------------------------------------------------------------
// Transpose + split: out_{b,s}[n][m] = split(in[m][n]); in is MxN fp32.
// ---------------------------------------------------------------------------
__global__ __launch_bounds__(256) void transpose_split_kernel(
    const float* __restrict__ in, bf16* __restrict__ ob, bf16* __restrict__ os,
    int M, int N, long long sIn, long long sOut)
{
    in += (long long)blockIdx.z * sIn;
    ob += (long long)blockIdx.z * sOut;
    os += (long long)blockIdx.z * sOut;
    __shared__ float t[32][33];
    const int bx = blockIdx.x * 32;   // n
    const int by = blockIdx.y * 32;   // m
    const int x = threadIdx.x, y = threadIdx.y;
#pragma unroll
    for (int i = 0; i < 32; i += 8)
        t[y + i][x] = in[(long long)(by + y + i) * N + bx + x];
    __syncthreads();
#pragma unroll
    for (int i = 0; i < 32; i += 8) {
        float v = t[x][y + i];
        bf16 b = __float2bfloat16(v);
        bf16 s = __float2bfloat16(v - __bfloat162float(b));
        const long long o = (long long)(bx + y + i) * M + by + x;
        ob[o] = b;
        os[o] = s;
    }
}

// ---------------------------------------------------------------------------
// Row softmax in-place (fp32) + bf16 big/small split outputs.
// One block per row of 2048; each thread owns 8 consecutive elements.
// ---------------------------------------------------------------------------
__global__ __launch_bounds__(256) void softmax_split_kernel(
    float* __restrict__ W, bf16* __restrict__ Pb, bf16* __restrict__ Ps)
{
    const long long base = (long long)blockIdx.x * SS;
    float* row = W + base;
    const int t = threadIdx.x;
    __shared__ float red[256];

    float4 a = *(float4*)(row + t * 8);
    float4 b = *(float4*)(row + t * 8 + 4);

    float mx = fmaxf(fmaxf(fmaxf(a.x, a.y), fmaxf(a.z, a.w)),
                     fmaxf(fmaxf(b.x, b.y), fmaxf(b.z, b.w)));
    red[t] = mx;
    __syncthreads();
    for (int s = 128; s > 0; s >>= 1) {
        if (t < s) red[t] = fmaxf(red[t], red[t + s]);
        __syncthreads();
    }
    mx = red[0];
    __syncthreads();

    a.x = expf(a.x - mx); a.y = expf(a.y - mx);
    a.z = expf(a.z - mx); a.w = expf(a.w - mx);
    b.x = expf(b.x - mx); b.y = expf(b.y - mx);
    b.z = expf(b.z - mx); b.w = expf(b.w - mx);
    float sum = a.x + a.y + a.z + a.w + b.x + b.y + b.z + b.w;
    red[t] = sum;
    __syncthreads();
    for (int s = 128; s > 0; s >>= 1) {
        if (t < s) red[t] += red[t + s];
        __syncthreads();
    }
    const float inv = 1.0f / red[0];
    a.x *= inv; a.y *= inv; a.z *= inv; a.w *= inv;
    b.x *= inv; b.y *= inv; b.z *= inv; b.w *= inv;

    *(float4*)(row + t * 8)     = a;
    *(float4*)(row + t * 8 + 4) = b;

    uint32_t bg[4], sm[4];
    split_pair(a.x, a.y, bg[0], sm[0]);
    split_pair(a.z, a.w, bg[1], sm[1]);
    split_pair(b.x, b.y, bg[2], sm[2]);
    split_pair(b.z, b.w, bg[3], sm[3]);
    *(uint4*)((char*)Pb + (base + t * 8) * 2) = make_uint4(bg[0], bg[1], bg[2], bg[3]);
    *(uint4*)((char*)Ps + (base + t * 8) * 2) = make_uint4(sm[0], sm[1], sm[2], sm[3]);
}

// ---------------------------------------------------------------------------
// kernel_launch — inputs: inputs, Wq, Wk, Wv, Wo, bo, scale
// output: [output (B*S*D)] [weights (B*S*S)]
// ---------------------------------------------------------------------------
extern "C" void kernel_launch(void* const* d_in, const int* in_sizes, int n_in,
                              void* d_out, int out_size)
{
    (void)in_sizes; (void)n_in; (void)out_size;
    const float* X     = (const float*)d_in[0];
    const float* Wq    = (const float*)d_in[1];
    const float* Wk    = (const float*)d_in[2];
    const float* Wv    = (const float*)d_in[3];
    const float* Wo    = (const float*)d_in[4];
    const float* bo    = (const float*)d_in[5];
    const float* scale = (const float*)d_in[6];

    float* out = (float*)d_out;                     // [B,S,D]
    float* wts = out + (long long)BB * SS * DD;     // [B,S,S]

    bf16 *xb, *xs, *qb, *qs, *kb, *ks, *vtb, *vts, *pb, *ps, *cb, *cs;
    bf16 *wqb, *wqs, *wkb, *wks, *wvb, *wvs, *wob, *wos;
    float* v;
    cudaGetSymbolAddress((void**)&xb,  g_xb);
    cudaGetSymbolAddress((void**)&xs,  g_xs);
    cudaGetSymbolAddress((void**)&qb,  g_qb);
    cudaGetSymbolAddress((void**)&qs,  g_qs);
    cudaGetSymbolAddress((void**)&kb,  g_kb);
    cudaGetSymbolAddress((void**)&ks,  g_ks);
    cudaGetSymbolAddress((void**)&v,   g_v);
    cudaGetSymbolAddress((void**)&vtb, g_vtb);
    cudaGetSymbolAddress((void**)&vts, g_vts);
    cudaGetSymbolAddress((void**)&pb,  g_pb);
    cudaGetSymbolAddress((void**)&ps,  g_ps);
    cudaGetSymbolAddress((void**)&cb,  g_cb);
    cudaGetSymbolAddress((void**)&cs,  g_cs);
    cudaGetSymbolAddress((void**)&wqb, g_wqb);
    cudaGetSymbolAddress((void**)&wqs, g_wqs);
    cudaGetSymbolAddress((void**)&wkb, g_wkb);
    cudaGetSymbolAddress((void**)&wks, g_wks);
    cudaGetSymbolAddress((void**)&wvb, g_wvb);
    cudaGetSymbolAddress((void**)&wvs, g_wvs);
    cudaGetSymbolAddress((void**)&wob, g_wob);
    cudaGetSymbolAddress((void**)&wos, g_wos);

    cudaFuncSetAttribute(gemm_bf16x3_kernel,
                         cudaFuncAttributeMaxDynamicSharedMemorySize, GEMM_SMEM);

    const dim3 tblk(32, 8);

    // Pre-split inputs: X elementwise; weights transposed to [N,K] K-major
    convert_split_kernel<<<(BB * SS * DD) / (256 * 4), 256>>>(X, xb, xs);
    transpose_split_kernel<<<dim3(32, 32, 1), tblk>>>(Wq, wqb, wqs, DD, UU, 0, 0);
    transpose_split_kernel<<<dim3(32, 32, 1), tblk>>>(Wk, wkb, wks, DD, UU, 0, 0);
    transpose_split_kernel<<<dim3(32, 32, 1), tblk>>>(Wv, wvb, wvs, DD, UU, 0, 0);
    transpose_split_kernel<<<dim3(32, 32, 1), tblk>>>(Wo, wob, wos, UU, DD, 0, 0);

    // 1) Q/K projections -> bf16 splits only; V -> fp32 (needs transpose)
    const dim3 g_qkv(UU / BN, (BB * SS) / BM, 1);
    gemm_bf16x3_kernel<<<g_qkv, 256, GEMM_SMEM>>>(
        xb, xs, wqb, wqs, nullptr, qb, qs, nullptr, nullptr,
        BB * SS, UU, DD, 0, 0, 0);
    gemm_bf16x3_kernel<<<g_qkv, 256, GEMM_SMEM>>>(
        xb, xs, wkb, wks, nullptr, kb, ks, nullptr, nullptr,
        BB * SS, UU, DD, 0, 0, 0);
    gemm_bf16x3_kernel<<<g_qkv, 256, GEMM_SMEM>>>(
        xb, xs, wvb, wvs, v, nullptr, nullptr, nullptr, nullptr,
        BB * SS, UU, DD, 0, 0, 0);

    // 2) scores = (Q @ K^T) * scale -> wts (fp32 output)
    const dim3 g_sc(SS / BN, SS / BM, BB);
    gemm_bf16x3_kernel<<<g_sc, 256, GEMM_SMEM>>>(
        qb, qs, kb, ks, wts, nullptr, nullptr, scale, nullptr,
        SS, SS, UU,
        (long long)SS * UU, (long long)SS * UU, (long long)SS * SS);

    // 3) softmax in place + split probs
    softmax_split_kernel<<<BB * SS, 256>>>(wts, pb, ps);

    // 4) transpose V per batch -> vt splits [U,S]
    transpose_split_kernel<<<dim3(UU / 32, SS / 32, BB), tblk>>>(
        v, vtb, vts, SS, UU, (long long)SS * UU, (long long)SS * UU);

    // 5) context = P @ V -> c splits
    const dim3 g_ctx(UU / BN, SS / BM, BB);
    gemm_bf16x3_kernel<<<g_ctx, 256, GEMM_SMEM>>>(
        pb, ps, vtb, vts, nullptr, cb, cs, nullptr, nullptr,
        SS, UU, SS,
        (long long)SS * SS, (long long)SS * UU, (long long)SS * UU);

    // 6) output = context @ Wo + bo (c is contiguous [B*S, U])
    const dim3 g_out(DD / BN, (BB * SS) / BM, 1);
    gemm_bf16x3_kernel<<<g_out, 256, GEMM_SMEM>>>(
        cb, cs, wob, wos, out, nullptr, nullptr, nullptr, bo,
        BB * SS, DD, UU, 0, 0, 0);
}

// round 13
// speedup vs baseline: 2.2099x; 1.0450x over previous
#include <cuda_runtime.h>
#include <cuda_bf16.h>
#include <math.h>
#include <stdint.h>

// ---------------------------------------------------------------------------
// Problem constants
// ---------------------------------------------------------------------------
#define BB 4
#define SS 2048
#define DD 1024
#define UU 1024

typedef __nv_bfloat16 bf16;

// GEMM tiling
#define BM 128
#define BN 128
#define KC 64                       // bf16 K elems per chunk (128B rows)
#define STAGES 3
#define TILE_BYTES (128 * 128)      // one 128x64 bf16 tile = 16 KB
#define STAGE_BYTES (4 * TILE_BYTES)
#define GEMM_SMEM (STAGES * STAGE_BYTES)   // 192 KB

// ---------------------------------------------------------------------------
// Scratch (device globals; allocations are forbidden)
// ---------------------------------------------------------------------------
static __device__ bf16  g_xb [(size_t)BB * SS * DD];
static __device__ bf16  g_xs [(size_t)BB * SS * DD];
static __device__ bf16  g_qb [(size_t)BB * SS * UU];
static __device__ bf16  g_qs [(size_t)BB * SS * UU];
static __device__ bf16  g_kb [(size_t)BB * SS * UU];
static __device__ bf16  g_ks [(size_t)BB * SS * UU];
static __device__ float g_v  [(size_t)BB * SS * UU];
static __device__ bf16  g_vtb[(size_t)BB * SS * UU];
static __device__ bf16  g_vts[(size_t)BB * SS * UU];
static __device__ bf16  g_pb [(size_t)BB * SS * SS];
static __device__ bf16  g_ps [(size_t)BB * SS * SS];
static __device__ bf16  g_cb [(size_t)BB * SS * UU];
static __device__ bf16  g_cs [(size_t)BB * SS * UU];
static __device__ bf16  g_wqb[(size_t)DD * UU];
static __device__ bf16  g_wqs[(size_t)DD * UU];
static __device__ bf16  g_wkb[(size_t)DD * UU];
static __device__ bf16  g_wks[(size_t)DD * UU];
static __device__ bf16  g_wvb[(size_t)DD * UU];
static __device__ bf16  g_wvs[(size_t)DD * UU];
static __device__ bf16  g_wob[(size_t)DD * UU];
static __device__ bf16  g_wos[(size_t)DD * UU];

// ---------------------------------------------------------------------------
// Base-ISA PTX helpers (no sm_103a-only features)
// ---------------------------------------------------------------------------
__device__ __forceinline__ uint32_t smem_u32_of(const void* p) {
    uint32_t a;
    asm("{ .reg .u64 t; cvta.to.shared.u64 t, %1; cvt.u32.u64 %0, t; }"
        : "=r"(a) : "l"(p));
    return a;
}

__device__ __forceinline__ void cp16(uint32_t dst, const void* src) {
    asm volatile("cp.async.cg.shared.global [%0], [%1], 16;"
                 :: "r"(dst), "l"(src) : "memory");
}
__device__ __forceinline__ void cp_commit() {
    asm volatile("cp.async.commit_group;" ::: "memory");
}
template <int N>
__device__ __forceinline__ void cp_wait() {
    asm volatile("cp.async.wait_group %0;" :: "n"(N) : "memory");
}

__device__ __forceinline__ void ldsm4(uint32_t* r, uint32_t addr) {
    asm volatile("ldmatrix.sync.aligned.m8n8.x4.shared.b16 {%0,%1,%2,%3}, [%4];"
                 : "=r"(r[0]), "=r"(r[1]), "=r"(r[2]), "=r"(r[3]) : "r"(addr));
}

__device__ __forceinline__ void mma16816(float* d, const uint32_t* a,
                                         uint32_t b0, uint32_t b1) {
    asm volatile(
        "mma.sync.aligned.m16n8k16.row.col.f32.bf16.bf16.f32 "
        "{%0,%1,%2,%3}, {%4,%5,%6,%7}, {%8,%9}, {%0,%1,%2,%3};"
        : "+f"(d[0]), "+f"(d[1]), "+f"(d[2]), "+f"(d[3])
        : "r"(a[0]), "r"(a[1]), "r"(a[2]), "r"(a[3]), "r"(b0), "r"(b1));
}

// Split a pair of fp32 into packed bf16 big + bf16 small (residual)
__device__ __forceinline__ void split_pair(float x, float y,
                                           uint32_t& big, uint32_t& sml) {
    __nv_bfloat162 b = __floats2bfloat162_rn(x, y);
    float bx = __bfloat162float(b.x), by = __bfloat162float(b.y);
    __nv_bfloat162 s = __floats2bfloat162_rn(x - bx, y - by);
    big = *reinterpret_cast<uint32_t*>(&b);
    sml = *reinterpret_cast<uint32_t*>(&s);
}

// ---------------------------------------------------------------------------
// Per-z operand/output pointer sets (z = blockIdx.z; max 4).
// Lets independent GEMMs (Q/K/V projections) or batched GEMMs share one
// launch so their scheduling tails merge.
// ---------------------------------------------------------------------------
struct ZPtrs {
    const bf16* Ab[4];
    const bf16* As[4];
    const bf16* Bb[4];
    const bf16* Bs[4];
    float*      C [4];
    bf16*       Ob[4];
    bf16*       Os[4];
};

// ---------------------------------------------------------------------------
// NT GEMM, bf16x3 fp32 emulation:
//   C[M,N] = (Ab+As)[M,K] * (Bb+Bs)[N,K]^T  (3 terms, AsBs dropped)
// Optional fp32 C (scaled, biased) and/or bf16 big/small split outputs.
// Operands pre-split bf16, K-major. M,N % 128 == 0, K % 64 == 0.
// ---------------------------------------------------------------------------
__global__ void __launch_bounds__(256) gemm_bf16x3_kernel(
    ZPtrs zp, const float* __restrict__ scale_ptr,
    const float* __restrict__ bias, int M, int N, int K)
{
    extern __shared__ char smem[];
    const int t  = threadIdx.x;
    const int m0 = blockIdx.y * BM;
    const int n0 = blockIdx.x * BN;
    const int z  = blockIdx.z;

    const char* pAb = (const char*)zp.Ab[z];
    const char* pAs = (const char*)zp.As[z];
    const char* pBb = (const char*)zp.Bb[z];
    const char* pBs = (const char*)zp.Bs[z];

    const uint32_t sbase = smem_u32_of(smem);
    const int nch = K / KC;
    const size_t ldb = (size_t)K * 2;     // row stride in bytes (A and B)

    // producer: 16 cp.async per thread per chunk; coalesced 128B rows,
    // XOR-swizzled smem (row*128 + ((kg ^ (row&7))<<4))
    const int prow = t >> 3;              // 0..31
    const int pkg  = t & 7;               // 0..7

#define PRODUCE(ch, st)                                                        \
    do {                                                                       \
        uint32_t s0 = sbase + (st) * STAGE_BYTES;                              \
        size_t colb = (size_t)(ch) * 128 + pkg * 16;                          \
        _Pragma("unroll")                                                      \
        for (int i = 0; i < 4; i++) {                                          \
            int row = i * 32 + prow;                                           \
            uint32_t so = (uint32_t)(row * 128 + ((pkg ^ (row & 7)) << 4));    \
            size_t ga = (size_t)(m0 + row) * ldb + colb;                       \
            size_t gb = (size_t)(n0 + row) * ldb + colb;                       \
            cp16(s0 + so,                  pAb + ga);                          \
            cp16(s0 + TILE_BYTES + so,     pAs + ga);                          \
            cp16(s0 + 2 * TILE_BYTES + so, pBb + gb);                          \
            cp16(s0 + 3 * TILE_BYTES + so, pBs + gb);                          \
        }                                                                      \
        cp_commit();                                                           \
    } while (0)

    PRODUCE(0, 0);
    PRODUCE(1, 1);

    // consumer layout: 8 warps = 2(M) x 4(N); warp tile 64x32
    const int lane = t & 31;
    const int wid  = t >> 5;
    const int wm   = (wid >> 2) * 64;
    const int wn   = (wid & 3) * 32;
    const int lrow = lane & 15;
    const int lkg  = lane >> 4;

    float acc[4][4][4];
#pragma unroll
    for (int i = 0; i < 4; i++)
#pragma unroll
        for (int j = 0; j < 4; j++)
#pragma unroll
            for (int r = 0; r < 4; r++) acc[i][j][r] = 0.0f;

    for (int ch = 0; ch < nch; ch++) {
        // One barrier per chunk. Invariant at top of iter ch: committed groups
        // are ids 0..ch+1 (or all, near tail); requiring id ch complete means
        // at most 1 outstanding (FIFO completion).
        if (ch + 1 < nch) cp_wait<1>(); else cp_wait<0>();
        __syncthreads();
        // produce(ch+2) writes stage (ch+2)%3 == (ch-1)%3, last read during
        // iter ch-1; the barrier above orders that read before this write.
        if (ch + 2 < nch) PRODUCE(ch + 2, (ch + 2) % STAGES);

        const uint32_t st = sbase + (ch % STAGES) * STAGE_BYTES;

#pragma unroll
        for (int ks = 0; ks < 4; ks++) {
            const int kg = ks * 2 + lkg;
            uint32_t a_b[4][4], a_s[4][4], b_b[2][4], b_s[2][4];
#pragma unroll
            for (int mt = 0; mt < 4; mt++) {
                int r = wm + mt * 16 + lrow;
                uint32_t off = (uint32_t)(r * 128 + ((kg ^ (r & 7)) << 4));
                ldsm4(a_b[mt], st + off);
                ldsm4(a_s[mt], st + TILE_BYTES + off);
            }
#pragma unroll
            for (int nt = 0; nt < 2; nt++) {
                int r = wn + nt * 16 + lrow;
                uint32_t off = (uint32_t)(r * 128 + ((kg ^ (r & 7)) << 4));
                ldsm4(b_b[nt], st + 2 * TILE_BYTES + off);
                ldsm4(b_s[nt], st + 3 * TILE_BYTES + off);
            }
#pragma unroll
            for (int mt = 0; mt < 4; mt++)
#pragma unroll
                for (int nt = 0; nt < 4; nt++) {
                    const uint32_t bb0 = b_b[nt >> 1][nt & 1];
                    const uint32_t bb1 = b_b[nt >> 1][(nt & 1) + 2];
                    const uint32_t bs0 = b_s[nt >> 1][nt & 1];
                    const uint32_t bs1 = b_s[nt >> 1][(nt & 1) + 2];
                    mma16816(acc[mt][nt], a_b[mt], bb0, bb1);   // big*big
                    mma16816(acc[mt][nt], a_b[mt], bs0, bs1);   // big*small
                    mma16816(acc[mt][nt], a_s[mt], bb0, bb1);   // small*big
                }
        }
    }
#undef PRODUCE

    // epilogue: c-frag lane l: (m = l/4 [+8], n = 2*(l%4)+{0,1})
    const float scl = scale_ptr ? *scale_ptr : 1.0f;
    float* pC  = zp.C[z];
    bf16*  pOb = zp.Ob[z];
    bf16*  pOs = zp.Os[z];
    const int l4 = lane >> 2;
    const int lc = (lane & 3) * 2;

#pragma unroll
    for (int mt = 0; mt < 4; mt++)
#pragma unroll
        for (int nt = 0; nt < 4; nt++) {
            const int r0  = m0 + wm + mt * 16 + l4;
            const int r1  = r0 + 8;
            const int col = n0 + wn + nt * 8 + lc;
            float v0 = acc[mt][nt][0] * scl;
            float v1 = acc[mt][nt][1] * scl;
            float v2 = acc[mt][nt][2] * scl;
            float v3 = acc[mt][nt][3] * scl;
            if (bias) {
                const float b0 = bias[col], b1 = bias[col + 1];
                v0 += b0; v1 += b1; v2 += b0; v3 += b1;
            }
            if (pC) {
                *(float2*)(pC + (long long)r0 * N + col) = make_float2(v0, v1);
                *(float2*)(pC + (long long)r1 * N + col) = make_float2(v2, v3);
            }
            if (pOb) {
                uint32_t bg, sm;
                split_pair(v0, v1, bg, sm);
                *(uint32_t*)(pOb + (long long)r0 * N + col) = bg;
                *(uint32_t*)(pOs + (long long)r0 * N + col) = sm;
                split_pair(v2, v3, bg, sm);
                *(uint32_t*)(pOb + (long long)r1 * N + col) = bg;
                *(uint32_t*)(pOs + (long long)r1 * N + col) = sm;
            }
        }
}

// ---------------------------------------------------------------------------
// Elementwise fp32 -> bf16 big/small split
// ---------------------------------------------------------------------------
__global__ __launch_bounds__(256) void convert_split_kernel(
    const float* __restrict__ in, bf16* __restrict__ ob, bf16* __restrict__ os)
{
    const long long i = (long long)blockIdx.x * 256 + threadIdx.x; // float4 idx
    float4 v = ((const float4*)in)[i];
    uint32_t b0, s0, b1, s1;
    split_pair(v.x, v.y, b0, s0);
    split_pair(v.z, v.w, b1, s1);
    ((uint2*)ob)[i] = make_uint2(b0, b1);
    ((uint2*)os)[i] = make_uint2(s0, s1);
}

// ---------------------------------------------------------------------------
// Batched 1024x1024 transpose+split for the 4 weight matrices (z selects).
// ---------------------------------------------------------------------------
struct T4Ptrs {
    const float* in[4];
    bf16* ob[4];
    bf16* os[4];
};

__global__ __launch_bounds__(256) void transpose_split4_kernel(T4Ptrs p)
{
    const int z = blockIdx.z;
    const float* in = p.in[z];
    bf16* ob = p.ob[z];
    bf16* os = p.os[z];
    __shared__ float t[32][33];
    const int bx = blockIdx.x * 32;   // n
    const int by = blockIdx.y * 32;   // m
    const int x = threadIdx.x, y = threadIdx.y;
#pragma unroll
    for (int i = 0; i < 32; i += 8)
        t[y + i][x] = in[(long long)(by + y + i) * DD + bx + x];
    __syncthreads();
#pragma unroll
    for (int i = 0; i < 32; i += 8) {
        float v = t[x][y + i];
        bf16 b = __float2bfloat16(v);
        bf16 s = __float2bfloat16(v - __bfloat162float(b));
        const long long o = (long long)(bx + y + i) * DD + by + x;
        ob[o] = b;
        os[o] = s;
    }
}

// ---------------------------------------------------------------------------
// Transpose + split (generic, batched via z): out[n][m] = split(in[m][n])
// ---------------------------------------------------------------------------
__global__ __launch_bounds__(256) void transpose_split_kernel(
    const float* __restrict__ in, bf16* __restrict__ ob, bf16* __restrict__ os,
    int M, int N, long long sIn, long long sOut)
{
    in += (long long)blockIdx.z * sIn;
    ob += (long long)blockIdx.z * sOut;
    os += (long long)blockIdx.z * sOut;
    __shared__ float t[32][33];
    const int bx = blockIdx.x * 32;   // n
    const int by = blockIdx.y * 32;   // m
    const int x = threadIdx.x, y = threadIdx.y;
#pragma unroll
    for (int i = 0; i < 32; i += 8)
        t[y + i][x] = in[(long long)(by + y + i) * N + bx + x];
    __syncthreads();
#pragma unroll
    for (int i = 0; i < 32; i += 8) {
        float v = t[x][y + i];
        bf16 b = __float2bfloat16(v);
        bf16 s = __float2bfloat16(v - __bfloat162float(b));
        const long long o = (long long)(bx + y + i) * M + by + x;
        ob[o] = b;
        os[o] = s;
    }
}

// ---------------------------------------------------------------------------
// Row softmax in-place (fp32) + bf16 big/small split outputs.
// One block per row of 2048; each thread owns 8 consecutive elements.
// ---------------------------------------------------------------------------
__global__ __launch_bounds__(256) void softmax_split_kernel(
    float* __restrict__ W, bf16* __restrict__ Pb, bf16* __restrict__ Ps)
{
    const long long base = (long long)blockIdx.x * SS;
    float* row = W + base;
    const int t = threadIdx.x;
    __shared__ float red[256];

    float4 a = *(float4*)(row + t * 8);
    float4 b = *(float4*)(row + t * 8 + 4);

    float mx = fmaxf(fmaxf(fmaxf(a.x, a.y), fmaxf(a.z, a.w)),
                     fmaxf(fmaxf(b.x, b.y), fmaxf(b.z, b.w)));
    red[t] = mx;
    __syncthreads();
    for (int s = 128; s > 0; s >>= 1) {
        if (t < s) red[t] = fmaxf(red[t], red[t + s]);
        __syncthreads();
    }
    mx = red[0];
    __syncthreads();

    a.x = __expf(a.x - mx); a.y = __expf(a.y - mx);
    a.z = __expf(a.z - mx); a.w = __expf(a.w - mx);
    b.x = __expf(b.x - mx); b.y = __expf(b.y - mx);
    b.z = __expf(b.z - mx); b.w = __expf(b.w - mx);
    float sum = a.x + a.y + a.z + a.w + b.x + b.y + b.z + b.w;
    red[t] = sum;
    __syncthreads();
    for (int s = 128; s > 0; s >>= 1) {
        if (t < s) red[t] += red[t + s];
        __syncthreads();
    }
    const float inv = 1.0f / red[0];
    a.x *= inv; a.y *= inv; a.z *= inv; a.w *= inv;
    b.x *= inv; b.y *= inv; b.z *= inv; b.w *= inv;

    *(float4*)(row + t * 8)     = a;
    *(float4*)(row + t * 8 + 4) = b;

    uint32_t bg[4], sm[4];
    split_pair(a.x, a.y, bg[0], sm[0]);
    split_pair(a.z, a.w, bg[1], sm[1]);
    split_pair(b.x, b.y, bg[2], sm[2]);
    split_pair(b.z, b.w, bg[3], sm[3]);
    *(uint4*)((char*)Pb + (base + t * 8) * 2) = make_uint4(bg[0], bg[1], bg[2], bg[3]);
    *(uint4*)((char*)Ps + (base + t * 8) * 2) = make_uint4(sm[0], sm[1], sm[2], sm[3]);
}

// ---------------------------------------------------------------------------
// kernel_launch — inputs: inputs, Wq, Wk, Wv, Wo, bo, scale
// output: [output (B*S*D)] [weights (B*S*S)]
// ---------------------------------------------------------------------------
extern "C" void kernel_launch(void* const* d_in, const int* in_sizes, int n_in,
                              void* d_out, int out_size)
{
    (void)in_sizes; (void)n_in; (void)out_size;
    const float* X     = (const float*)d_in[0];
    const float* Wq    = (const float*)d_in[1];
    const float* Wk    = (const float*)d_in[2];
    const float* Wv    = (const float*)d_in[3];
    const float* Wo    = (const float*)d_in[4];
    const float* bo    = (const float*)d_in[5];
    const float* scale = (const float*)d_in[6];

    float* out = (float*)d_out;                     // [B,S,D]
    float* wts = out + (long long)BB * SS * DD;     // [B,S,S]

    bf16 *xb, *xs, *qb, *qs, *kb, *ks, *vtb, *vts, *pb, *ps, *cb, *cs;
    bf16 *wqb, *wqs, *wkb, *wks, *wvb, *wvs, *wob, *wos;
    float* v;
    cudaGetSymbolAddress((void**)&xb,  g_xb);
    cudaGetSymbolAddress((void**)&xs,  g_xs);
    cudaGetSymbolAddress((void**)&qb,  g_qb);
    cudaGetSymbolAddress((void**)&qs,  g_qs);
    cudaGetSymbolAddress((void**)&kb,  g_kb);
    cudaGetSymbolAddress((void**)&ks,  g_ks);
    cudaGetSymbolAddress((void**)&v,   g_v);
    cudaGetSymbolAddress((void**)&vtb, g_vtb);
    cudaGetSymbolAddress((void**)&vts, g_vts);
    cudaGetSymbolAddress((void**)&pb,  g_pb);
    cudaGetSymbolAddress((void**)&ps,  g_ps);
    cudaGetSymbolAddress((void**)&cb,  g_cb);
    cudaGetSymbolAddress((void**)&cs,  g_cs);
    cudaGetSymbolAddress((void**)&wqb, g_wqb);
    cudaGetSymbolAddress((void**)&wqs, g_wqs);
    cudaGetSymbolAddress((void**)&wkb, g_wkb);
    cudaGetSymbolAddress((void**)&wks, g_wks);
    cudaGetSymbolAddress((void**)&wvb, g_wvb);
    cudaGetSymbolAddress((void**)&wvs, g_wvs);
    cudaGetSymbolAddress((void**)&wob, g_wob);
    cudaGetSymbolAddress((void**)&wos, g_wos);

    cudaFuncSetAttribute(gemm_bf16x3_kernel,
                         cudaFuncAttributeMaxDynamicSharedMemorySize, GEMM_SMEM);

    // 1) X split + all 4 weight transposes (one batched launch)
    convert_split_kernel<<<(BB * SS * DD) / (256 * 4), 256>>>(X, xb, xs);
    {
        T4Ptrs tp{};
        tp.in[0] = Wq;  tp.ob[0] = wqb; tp.os[0] = wqs;
        tp.in[1] = Wk;  tp.ob[1] = wkb; tp.os[1] = wks;
        tp.in[2] = Wv;  tp.ob[2] = wvb; tp.os[2] = wvs;
        tp.in[3] = Wo;  tp.ob[3] = wob; tp.os[3] = wos;
        transpose_split4_kernel<<<dim3(32, 32, 4), dim3(32, 8)>>>(tp);
    }

    // 2) Q/K/V projections merged into ONE launch (z selects weights+outputs)
    {
        ZPtrs zp{};
        for (int z = 0; z < 3; z++) { zp.Ab[z] = xb; zp.As[z] = xs; }
        zp.Bb[0] = wqb; zp.Bs[0] = wqs; zp.Ob[0] = qb; zp.Os[0] = qs;
        zp.Bb[1] = wkb; zp.Bs[1] = wks; zp.Ob[1] = kb; zp.Os[1] = ks;
        zp.Bb[2] = wvb; zp.Bs[2] = wvs; zp.C[2]  = v;
        gemm_bf16x3_kernel<<<dim3(UU / BN, (BB * SS) / BM, 3), 256, GEMM_SMEM>>>(
            zp, nullptr, nullptr, BB * SS, UU, DD);
    }

    // 3) scores = (Q @ K^T) * scale -> wts (fp32), batched over B via z
    {
        ZPtrs zp{};
        for (int z = 0; z < BB; z++) {
            zp.Ab[z] = qb + (long long)z * SS * UU;
            zp.As[z] = qs + (long long)z * SS * UU;
            zp.Bb[z] = kb + (long long)z * SS * UU;
            zp.Bs[z] = ks + (long long)z * SS * UU;
            zp.C[z]  = wts + (long long)z * SS * SS;
        }
        gemm_bf16x3_kernel<<<dim3(SS / BN, SS / BM, BB), 256, GEMM_SMEM>>>(
            zp, scale, nullptr, SS, SS, UU);
    }

    // 4) softmax in place + split probs
    softmax_split_kernel<<<BB * SS, 256>>>(wts, pb, ps);

    // 5) transpose V per batch -> vt splits [U,S]
    transpose_split_kernel<<<dim3(UU / 32, SS / 32, BB), dim3(32, 8)>>>(
        v, vtb, vts, SS, UU, (long long)SS * UU, (long long)SS * UU);

    // 6) context = P @ V -> c splits, batched over B via z
    {
        ZPtrs zp{};
        for (int z = 0; z < BB; z++) {
            zp.Ab[z] = pb  + (long long)z * SS * SS;
            zp.As[z] = ps  + (long long)z * SS * SS;
            zp.Bb[z] = vtb + (long long)z * SS * UU;
            zp.Bs[z] = vts + (long long)z * SS * UU;
            zp.Ob[z] = cb  + (long long)z * SS * UU;
            zp.Os[z] = cs  + (long long)z * SS * UU;
        }
        gemm_bf16x3_kernel<<<dim3(UU / BN, SS / BM, BB), 256, GEMM_SMEM>>>(
            zp, nullptr, nullptr, SS, UU, SS);
    }

    // 7) output = context @ Wo + bo
    {
        ZPtrs zp{};
        zp.Ab[0] = cb; zp.As[0] = cs;
        zp.Bb[0] = wob; zp.Bs[0] = wos;
        zp.C[0]  = out;
        gemm_bf16x3_kernel<<<dim3(DD / BN, (BB * SS) / BM, 1), 256, GEMM_SMEM>>>(
            zp, nullptr, bo, BB * SS, DD, UU);
    }
}

// round 14
// speedup vs baseline: 2.2133x; 1.0015x over previous
#include <cuda_runtime.h>
#include <cuda_bf16.h>
#include <math.h>
#include <stdint.h>

// ---------------------------------------------------------------------------
// Problem constants
// ---------------------------------------------------------------------------
#define BB 4
#define SS 2048
#define DD 1024
#define UU 1024

typedef __nv_bfloat16 bf16;

// GEMM tiling
#define BM 128
#define BN 128
#define KC 64                       // bf16 K elems per chunk (128B rows)
#define STAGES 3
#define TILE_BYTES (128 * 128)      // one 128x64 bf16 tile = 16 KB
#define STAGE_BYTES (4 * TILE_BYTES)
#define GEMM_SMEM (STAGES * STAGE_BYTES)   // 192 KB

// ---------------------------------------------------------------------------
// Scratch (device globals; allocations are forbidden)
// ---------------------------------------------------------------------------
static __device__ bf16  g_xb [(size_t)BB * SS * DD];
static __device__ bf16  g_xs [(size_t)BB * SS * DD];
static __device__ bf16  g_qb [(size_t)BB * SS * UU];
static __device__ bf16  g_qs [(size_t)BB * SS * UU];
static __device__ bf16  g_kb [(size_t)BB * SS * UU];
static __device__ bf16  g_ks [(size_t)BB * SS * UU];
static __device__ float g_v  [(size_t)BB * SS * UU];
static __device__ bf16  g_vtb[(size_t)BB * SS * UU];
static __device__ bf16  g_vts[(size_t)BB * SS * UU];
static __device__ bf16  g_pb [(size_t)BB * SS * SS];
static __device__ bf16  g_ps [(size_t)BB * SS * SS];
static __device__ bf16  g_cb [(size_t)BB * SS * UU];
static __device__ bf16  g_cs [(size_t)BB * SS * UU];
static __device__ bf16  g_wqb[(size_t)DD * UU];
static __device__ bf16  g_wqs[(size_t)DD * UU];
static __device__ bf16  g_wkb[(size_t)DD * UU];
static __device__ bf16  g_wks[(size_t)DD * UU];
static __device__ bf16  g_wvb[(size_t)DD * UU];
static __device__ bf16  g_wvs[(size_t)DD * UU];
static __device__ bf16  g_wob[(size_t)DD * UU];
static __device__ bf16  g_wos[(size_t)DD * UU];

// ---------------------------------------------------------------------------
// Base-ISA PTX helpers (no sm_103a-only features)
// ---------------------------------------------------------------------------
__device__ __forceinline__ uint32_t smem_u32_of(const void* p) {
    uint32_t a;
    asm("{ .reg .u64 t; cvta.to.shared.u64 t, %1; cvt.u32.u64 %0, t; }"
        : "=r"(a) : "l"(p));
    return a;
}

__device__ __forceinline__ void cp16(uint32_t dst, const void* src) {
    asm volatile("cp.async.cg.shared.global [%0], [%1], 16;"
                 :: "r"(dst), "l"(src) : "memory");
}
__device__ __forceinline__ void cp_commit() {
    asm volatile("cp.async.commit_group;" ::: "memory");
}
template <int N>
__device__ __forceinline__ void cp_wait() {
    asm volatile("cp.async.wait_group %0;" :: "n"(N) : "memory");
}

__device__ __forceinline__ void ldsm4(uint32_t* r, uint32_t addr) {
    asm volatile("ldmatrix.sync.aligned.m8n8.x4.shared.b16 {%0,%1,%2,%3}, [%4];"
                 : "=r"(r[0]), "=r"(r[1]), "=r"(r[2]), "=r"(r[3]) : "r"(addr));
}

__device__ __forceinline__ void mma16816(float* d, const uint32_t* a,
                                         uint32_t b0, uint32_t b1) {
    asm volatile(
        "mma.sync.aligned.m16n8k16.row.col.f32.bf16.bf16.f32 "
        "{%0,%1,%2,%3}, {%4,%5,%6,%7}, {%8,%9}, {%0,%1,%2,%3};"
        : "+f"(d[0]), "+f"(d[1]), "+f"(d[2]), "+f"(d[3])
        : "r"(a[0]), "r"(a[1]), "r"(a[2]), "r"(a[3]), "r"(b0), "r"(b1));
}

// Split a pair of fp32 into packed bf16 big + bf16 small (residual)
__device__ __forceinline__ void split_pair(float x, float y,
                                           uint32_t& big, uint32_t& sml) {
    __nv_bfloat162 b = __floats2bfloat162_rn(x, y);
    float bx = __bfloat162float(b.x), by = __bfloat162float(b.y);
    __nv_bfloat162 s = __floats2bfloat162_rn(x - bx, y - by);
    big = *reinterpret_cast<uint32_t*>(&b);
    sml = *reinterpret_cast<uint32_t*>(&s);
}

// ---------------------------------------------------------------------------
// Per-z operand/output pointer sets (z = blockIdx.z; max 4).
// Lets independent GEMMs (Q/K/V projections) or batched GEMMs share one
// launch so their scheduling tails merge.
// ---------------------------------------------------------------------------
struct ZPtrs {
    const bf16* Ab[4];
    const bf16* As[4];
    const bf16* Bb[4];
    const bf16* Bs[4];
    float*      C [4];
    bf16*       Ob[4];
    bf16*       Os[4];
};

// ---------------------------------------------------------------------------
// NT GEMM, bf16x3 fp32 emulation:
//   C[M,N] = (Ab+As)[M,K] * (Bb+Bs)[N,K]^T  (3 terms, AsBs dropped)
// Optional fp32 C (scaled, biased) and/or bf16 big/small split outputs.
// Operands pre-split bf16, K-major. M,N % 128 == 0, K % 64 == 0.
// ---------------------------------------------------------------------------
__global__ void __launch_bounds__(256) gemm_bf16x3_kernel(
    ZPtrs zp, const float* __restrict__ scale_ptr,
    const float* __restrict__ bias, int M, int N, int K)
{
    extern __shared__ char smem[];
    const int t  = threadIdx.x;
    const int m0 = blockIdx.y * BM;
    const int n0 = blockIdx.x * BN;
    const int z  = blockIdx.z;

    const char* pAb = (const char*)zp.Ab[z];
    const char* pAs = (const char*)zp.As[z];
    const char* pBb = (const char*)zp.Bb[z];
    const char* pBs = (const char*)zp.Bs[z];

    const uint32_t sbase = smem_u32_of(smem);
    const int nch = K / KC;
    const size_t ldb = (size_t)K * 2;     // row stride in bytes (A and B)

    // producer: 16 cp.async per thread per chunk; coalesced 128B rows,
    // XOR-swizzled smem (row*128 + ((kg ^ (row&7))<<4))
    const int prow = t >> 3;              // 0..31
    const int pkg  = t & 7;               // 0..7

#define PRODUCE(ch, st)                                                        \
    do {                                                                       \
        uint32_t s0 = sbase + (st) * STAGE_BYTES;                              \
        size_t colb = (size_t)(ch) * 128 + pkg * 16;                          \
        _Pragma("unroll")                                                      \
        for (int i = 0; i < 4; i++) {                                          \
            int row = i * 32 + prow;                                           \
            uint32_t so = (uint32_t)(row * 128 + ((pkg ^ (row & 7)) << 4));    \
            size_t ga = (size_t)(m0 + row) * ldb + colb;                       \
            size_t gb = (size_t)(n0 + row) * ldb + colb;                       \
            cp16(s0 + so,                  pAb + ga);                          \
            cp16(s0 + TILE_BYTES + so,     pAs + ga);                          \
            cp16(s0 + 2 * TILE_BYTES + so, pBb + gb);                          \
            cp16(s0 + 3 * TILE_BYTES + so, pBs + gb);                          \
        }                                                                      \
        cp_commit();                                                           \
    } while (0)

    PRODUCE(0, 0);
    PRODUCE(1, 1);

    // consumer layout: 8 warps = 2(M) x 4(N); warp tile 64x32
    const int lane = t & 31;
    const int wid  = t >> 5;
    const int wm   = (wid >> 2) * 64;
    const int wn   = (wid & 3) * 32;
    const int lrow = lane & 15;
    const int lkg  = lane >> 4;

    float acc[4][4][4];
#pragma unroll
    for (int i = 0; i < 4; i++)
#pragma unroll
        for (int j = 0; j < 4; j++)
#pragma unroll
            for (int r = 0; r < 4; r++) acc[i][j][r] = 0.0f;

    for (int ch = 0; ch < nch; ch++) {
        // One barrier per chunk. Invariant at top of iter ch: committed groups
        // are ids 0..ch+1 (or all, near tail); requiring id ch complete means
        // at most 1 outstanding (FIFO completion).
        if (ch + 1 < nch) cp_wait<1>(); else cp_wait<0>();
        __syncthreads();
        // produce(ch+2) writes stage (ch+2)%3 == (ch-1)%3, last read during
        // iter ch-1; the barrier above orders that read before this write.
        if (ch + 2 < nch) PRODUCE(ch + 2, (ch + 2) % STAGES);

        const uint32_t st = sbase + (ch % STAGES) * STAGE_BYTES;

#pragma unroll
        for (int ks = 0; ks < 4; ks++) {
            const int kg = ks * 2 + lkg;
            uint32_t a_b[4][4], a_s[4][4], b_b[2][4], b_s[2][4];
#pragma unroll
            for (int mt = 0; mt < 4; mt++) {
                int r = wm + mt * 16 + lrow;
                uint32_t off = (uint32_t)(r * 128 + ((kg ^ (r & 7)) << 4));
                ldsm4(a_b[mt], st + off);
                ldsm4(a_s[mt], st + TILE_BYTES + off);
            }
#pragma unroll
            for (int nt = 0; nt < 2; nt++) {
                int r = wn + nt * 16 + lrow;
                uint32_t off = (uint32_t)(r * 128 + ((kg ^ (r & 7)) << 4));
                ldsm4(b_b[nt], st + 2 * TILE_BYTES + off);
                ldsm4(b_s[nt], st + 3 * TILE_BYTES + off);
            }
#pragma unroll
            for (int mt = 0; mt < 4; mt++)
#pragma unroll
                for (int nt = 0; nt < 4; nt++) {
                    const uint32_t bb0 = b_b[nt >> 1][nt & 1];
                    const uint32_t bb1 = b_b[nt >> 1][(nt & 1) + 2];
                    const uint32_t bs0 = b_s[nt >> 1][nt & 1];
                    const uint32_t bs1 = b_s[nt >> 1][(nt & 1) + 2];
                    mma16816(acc[mt][nt], a_b[mt], bb0, bb1);   // big*big
                    mma16816(acc[mt][nt], a_b[mt], bs0, bs1);   // big*small
                    mma16816(acc[mt][nt], a_s[mt], bb0, bb1);   // small*big
                }
        }
    }
#undef PRODUCE

    // epilogue: c-frag lane l: (m = l/4 [+8], n = 2*(l%4)+{0,1})
    const float scl = scale_ptr ? *scale_ptr : 1.0f;
    float* pC  = zp.C[z];
    bf16*  pOb = zp.Ob[z];
    bf16*  pOs = zp.Os[z];
    const int l4 = lane >> 2;
    const int lc = (lane & 3) * 2;

#pragma unroll
    for (int mt = 0; mt < 4; mt++)
#pragma unroll
        for (int nt = 0; nt < 4; nt++) {
            const int r0  = m0 + wm + mt * 16 + l4;
            const int r1  = r0 + 8;
            const int col = n0 + wn + nt * 8 + lc;
            float v0 = acc[mt][nt][0] * scl;
            float v1 = acc[mt][nt][1] * scl;
            float v2 = acc[mt][nt][2] * scl;
            float v3 = acc[mt][nt][3] * scl;
            if (bias) {
                const float b0 = bias[col], b1 = bias[col + 1];
                v0 += b0; v1 += b1; v2 += b0; v3 += b1;
            }
            if (pC) {
                *(float2*)(pC + (long long)r0 * N + col) = make_float2(v0, v1);
                *(float2*)(pC + (long long)r1 * N + col) = make_float2(v2, v3);
            }
            if (pOb) {
                uint32_t bg, sm;
                split_pair(v0, v1, bg, sm);
                *(uint32_t*)(pOb + (long long)r0 * N + col) = bg;
                *(uint32_t*)(pOs + (long long)r0 * N + col) = sm;
                split_pair(v2, v3, bg, sm);
                *(uint32_t*)(pOb + (long long)r1 * N + col) = bg;
                *(uint32_t*)(pOs + (long long)r1 * N + col) = sm;
            }
        }
}

// ---------------------------------------------------------------------------
// Elementwise fp32 -> bf16 big/small split
// ---------------------------------------------------------------------------
__global__ __launch_bounds__(256) void convert_split_kernel(
    const float* __restrict__ in, bf16* __restrict__ ob, bf16* __restrict__ os)
{
    const long long i = (long long)blockIdx.x * 256 + threadIdx.x; // float4 idx
    float4 v = ((const float4*)in)[i];
    uint32_t b0, s0, b1, s1;
    split_pair(v.x, v.y, b0, s0);
    split_pair(v.z, v.w, b1, s1);
    ((uint2*)ob)[i] = make_uint2(b0, b1);
    ((uint2*)os)[i] = make_uint2(s0, s1);
}

// ---------------------------------------------------------------------------
// Batched 1024x1024 transpose+split for the 4 weight matrices (z selects).
// ---------------------------------------------------------------------------
struct T4Ptrs {
    const float* in[4];
    bf16* ob[4];
    bf16* os[4];
};

__global__ __launch_bounds__(256) void transpose_split4_kernel(T4Ptrs p)
{
    const int z = blockIdx.z;
    const float* in = p.in[z];
    bf16* ob = p.ob[z];
    bf16* os = p.os[z];
    __shared__ float t[32][33];
    const int bx = blockIdx.x * 32;   // n
    const int by = blockIdx.y * 32;   // m
    const int x = threadIdx.x, y = threadIdx.y;
#pragma unroll
    for (int i = 0; i < 32; i += 8)
        t[y + i][x] = in[(long long)(by + y + i) * DD + bx + x];
    __syncthreads();
#pragma unroll
    for (int i = 0; i < 32; i += 8) {
        float v = t[x][y + i];
        bf16 b = __float2bfloat16(v);
        bf16 s = __float2bfloat16(v - __bfloat162float(b));
        const long long o = (long long)(bx + y + i) * DD + by + x;
        ob[o] = b;
        os[o] = s;
    }
}

// ---------------------------------------------------------------------------
// Transpose + split (generic, batched via z): out[n][m] = split(in[m][n])
// ---------------------------------------------------------------------------
__global__ __launch_bounds__(256) void transpose_split_kernel(
    const float* __restrict__ in, bf16* __restrict__ ob, bf16* __restrict__ os,
    int M, int N, long long sIn, long long sOut)
{
    in += (long long)blockIdx.z * sIn;
    ob += (long long)blockIdx.z * sOut;
    os += (long long)blockIdx.z * sOut;
    __shared__ float t[32][33];
    const int bx = blockIdx.x * 32;   // n
    const int by = blockIdx.y * 32;   // m
    const int x = threadIdx.x, y = threadIdx.y;
#pragma unroll
    for (int i = 0; i < 32; i += 8)
        t[y + i][x] = in[(long long)(by + y + i) * N + bx + x];
    __syncthreads();
#pragma unroll
    for (int i = 0; i < 32; i += 8) {
        float v = t[x][y + i];
        bf16 b = __float2bfloat16(v);
        bf16 s = __float2bfloat16(v - __bfloat162float(b));
        const long long o = (long long)(bx + y + i) * M + by + x;
        ob[o] = b;
        os[o] = s;
    }
}

// ---------------------------------------------------------------------------
// Row softmax in-place (fp32) + bf16 big/small split outputs.
// One block per row of 2048; each thread owns 8 consecutive elements.
// ---------------------------------------------------------------------------
__global__ __launch_bounds__(256) void softmax_split_kernel(
    float* __restrict__ W, bf16* __restrict__ Pb, bf16* __restrict__ Ps)
{
    const long long base = (long long)blockIdx.x * SS;
    float* row = W + base;
    const int t = threadIdx.x;
    __shared__ float red[256];

    float4 a = *(float4*)(row + t * 8);
    float4 b = *(float4*)(row + t * 8 + 4);

    float mx = fmaxf(fmaxf(fmaxf(a.x, a.y), fmaxf(a.z, a.w)),
                     fmaxf(fmaxf(b.x, b.y), fmaxf(b.z, b.w)));
    red[t] = mx;
    __syncthreads();
    for (int s = 128; s > 0; s >>= 1) {
        if (t < s) red[t] = fmaxf(red[t], red[t + s]);
        __syncthreads();
    }
    mx = red[0];
    __syncthreads();

    a.x = __expf(a.x - mx); a.y = __expf(a.y - mx);
    a.z = __expf(a.z - mx); a.w = __expf(a.w - mx);
    b.x = __expf(b.x - mx); b.y = __expf(b.y - mx);
    b.z = __expf(b.z - mx); b.w = __expf(b.w - mx);
    float sum = a.x + a.y + a.z + a.w + b.x + b.y + b.z + b.w;
    red[t] = sum;
    __syncthreads();
    for (int s = 128; s > 0; s >>= 1) {
        if (t < s) red[t] += red[t + s];
        __syncthreads();
    }
    const float inv = 1.0f / red[0];
    a.x *= inv; a.y *= inv; a.z *= inv; a.w *= inv;
    b.x *= inv; b.y *= inv; b.z *= inv; b.w *= inv;

    *(float4*)(row + t * 8)     = a;
    *(float4*)(row + t * 8 + 4) = b;

    uint32_t bg[4], sm[4];
    split_pair(a.x, a.y, bg[0], sm[0]);
    split_pair(a.z, a.w, bg[1], sm[1]);
    split_pair(b.x, b.y, bg[2], sm[2]);
    split_pair(b.z, b.w, bg[3], sm[3]);
    *(uint4*)((char*)Pb + (base + t * 8) * 2) = make_uint4(bg[0], bg[1], bg[2], bg[3]);
    *(uint4*)((char*)Ps + (base + t * 8) * 2) = make_uint4(sm[0], sm[1], sm[2], sm[3]);
}

// ---------------------------------------------------------------------------
// kernel_launch — inputs: inputs, Wq, Wk, Wv, Wo, bo, scale
// output: [output (B*S*D)] [weights (B*S*S)]
// ---------------------------------------------------------------------------
extern "C" void kernel_launch(void* const* d_in, const int* in_sizes, int n_in,
                              void* d_out, int out_size)
{
    (void)in_sizes; (void)n_in; (void)out_size;
    const float* X     = (const float*)d_in[0];
    const float* Wq    = (const float*)d_in[1];
    const float* Wk    = (const float*)d_in[2];
    const float* Wv    = (const float*)d_in[3];
    const float* Wo    = (const float*)d_in[4];
    const float* bo    = (const float*)d_in[5];
    const float* scale = (const float*)d_in[6];

    float* out = (float*)d_out;                     // [B,S,D]
    float* wts = out + (long long)BB * SS * DD;     // [B,S,S]

    bf16 *xb, *xs, *qb, *qs, *kb, *ks, *vtb, *vts, *pb, *ps, *cb, *cs;
    bf16 *wqb, *wqs, *wkb, *wks, *wvb, *wvs, *wob, *wos;
    float* v;
    cudaGetSymbolAddress((void**)&xb,  g_xb);
    cudaGetSymbolAddress((void**)&xs,  g_xs);
    cudaGetSymbolAddress((void**)&qb,  g_qb);
    cudaGetSymbolAddress((void**)&qs,  g_qs);
    cudaGetSymbolAddress((void**)&kb,  g_kb);
    cudaGetSymbolAddress((void**)&ks,  g_ks);
    cudaGetSymbolAddress((void**)&v,   g_v);
    cudaGetSymbolAddress((void**)&vtb, g_vtb);
    cudaGetSymbolAddress((void**)&vts, g_vts);
    cudaGetSymbolAddress((void**)&pb,  g_pb);
    cudaGetSymbolAddress((void**)&ps,  g_ps);
    cudaGetSymbolAddress((void**)&cb,  g_cb);
    cudaGetSymbolAddress((void**)&cs,  g_cs);
    cudaGetSymbolAddress((void**)&wqb, g_wqb);
    cudaGetSymbolAddress((void**)&wqs, g_wqs);
    cudaGetSymbolAddress((void**)&wkb, g_wkb);
    cudaGetSymbolAddress((void**)&wks, g_wks);
    cudaGetSymbolAddress((void**)&wvb, g_wvb);
    cudaGetSymbolAddress((void**)&wvs, g_wvs);
    cudaGetSymbolAddress((void**)&wob, g_wob);
    cudaGetSymbolAddress((void**)&wos, g_wos);

    cudaFuncSetAttribute(gemm_bf16x3_kernel,
                         cudaFuncAttributeMaxDynamicSharedMemorySize, GEMM_SMEM);

    // 1) X split + all 4 weight transposes (one batched launch)
    convert_split_kernel<<<(BB * SS * DD) / (256 * 4), 256>>>(X, xb, xs);
    {
        T4Ptrs tp{};
        tp.in[0] = Wq;  tp.ob[0] = wqb; tp.os[0] = wqs;
        tp.in[1] = Wk;  tp.ob[1] = wkb; tp.os[1] = wks;
        tp.in[2] = Wv;  tp.ob[2] = wvb; tp.os[2] = wvs;
        tp.in[3] = Wo;  tp.ob[3] = wob; tp.os[3] = wos;
        transpose_split4_kernel<<<dim3(32, 32, 4), dim3(32, 8)>>>(tp);
    }

    // 2) Q/K/V projections merged into ONE launch (z selects weights+outputs)
    {
        ZPtrs zp{};
        for (int z = 0; z < 3; z++) { zp.Ab[z] = xb; zp.As[z] = xs; }
        zp.Bb[0] = wqb; zp.Bs[0] = wqs; zp.Ob[0] = qb; zp.Os[0] = qs;
        zp.Bb[1] = wkb; zp.Bs[1] = wks; zp.Ob[1] = kb; zp.Os[1] = ks;
        zp.Bb[2] = wvb; zp.Bs[2] = wvs; zp.C[2]  = v;
        gemm_bf16x3_kernel<<<dim3(UU / BN, (BB * SS) / BM, 3), 256, GEMM_SMEM>>>(
            zp, nullptr, nullptr, BB * SS, UU, DD);
    }

    // 3) scores = (Q @ K^T) * scale -> wts (fp32), batched over B via z
    {
        ZPtrs zp{};
        for (int z = 0; z < BB; z++) {
            zp.Ab[z] = qb + (long long)z * SS * UU;
            zp.As[z] = qs + (long long)z * SS * UU;
            zp.Bb[z] = kb + (long long)z * SS * UU;
            zp.Bs[z] = ks + (long long)z * SS * UU;
            zp.C[z]  = wts + (long long)z * SS * SS;
        }
        gemm_bf16x3_kernel<<<dim3(SS / BN, SS / BM, BB), 256, GEMM_SMEM>>>(
            zp, scale, nullptr, SS, SS, UU);
    }

    // 4) softmax in place + split probs
    softmax_split_kernel<<<BB * SS, 256>>>(wts, pb, ps);

    // 5) transpose V per batch -> vt splits [U,S]
    transpose_split_kernel<<<dim3(UU / 32, SS / 32, BB), dim3(32, 8)>>>(
        v, vtb, vts, SS, UU, (long long)SS * UU, (long long)SS * UU);

    // 6) context = P @ V -> c splits, batched over B via z
    {
        ZPtrs zp{};
        for (int z = 0; z < BB; z++) {
            zp.Ab[z] = pb  + (long long)z * SS * SS;
            zp.As[z] = ps  + (long long)z * SS * SS;
            zp.Bb[z] = vtb + (long long)z * SS * UU;
            zp.Bs[z] = vts + (long long)z * SS * UU;
            zp.Ob[z] = cb  + (long long)z * SS * UU;
            zp.Os[z] = cs  + (long long)z * SS * UU;
        }
        gemm_bf16x3_kernel<<<dim3(UU / BN, SS / BM, BB), 256, GEMM_SMEM>>>(
            zp, nullptr, nullptr, SS, UU, SS);
    }

    // 7) output = context @ Wo + bo
    {
        ZPtrs zp{};
        zp.Ab[0] = cb; zp.As[0] = cs;
        zp.Bb[0] = wob; zp.Bs[0] = wos;
        zp.C[0]  = out;
        gemm_bf16x3_kernel<<<dim3(DD / BN, (BB * SS) / BM, 1), 256, GEMM_SMEM>>>(
            zp, nullptr, bo, BB * SS, DD, UU);
    }
}

// round 15
// speedup vs baseline: 2.2293x; 1.0072x over previous
#include <cuda_runtime.h>
#include <cuda_bf16.h>
#include <math.h>
#include <stdint.h>

// ---------------------------------------------------------------------------
// Problem constants
// ---------------------------------------------------------------------------
#define BB 4
#define SS 2048
#define DD 1024
#define UU 1024

typedef __nv_bfloat16 bf16;

// GEMM tiling
#define BM 128
#define BN 128
#define KC 64                       // bf16 K elems per chunk (128B rows)
#define STAGES 3
#define TILE_BYTES (128 * 128)      // one 128x64 bf16 tile = 16 KB
#define STAGE_BYTES (4 * TILE_BYTES)
#define GEMM_SMEM (STAGES * STAGE_BYTES)   // 192 KB

// ---------------------------------------------------------------------------
// Scratch (device globals; allocations are forbidden)
// ---------------------------------------------------------------------------
static __device__ bf16  g_xb [(size_t)BB * SS * DD];
static __device__ bf16  g_xs [(size_t)BB * SS * DD];
static __device__ bf16  g_qb [(size_t)BB * SS * UU];
static __device__ bf16  g_qs [(size_t)BB * SS * UU];
static __device__ bf16  g_kb [(size_t)BB * SS * UU];
static __device__ bf16  g_ks [(size_t)BB * SS * UU];
static __device__ float g_v  [(size_t)BB * SS * UU];
static __device__ bf16  g_vtb[(size_t)BB * SS * UU];
static __device__ bf16  g_vts[(size_t)BB * SS * UU];
static __device__ bf16  g_pb [(size_t)BB * SS * SS];
static __device__ bf16  g_ps [(size_t)BB * SS * SS];
static __device__ bf16  g_cb [(size_t)BB * SS * UU];
static __device__ bf16  g_cs [(size_t)BB * SS * UU];
static __device__ bf16  g_wqb[(size_t)DD * UU];
static __device__ bf16  g_wqs[(size_t)DD * UU];
static __device__ bf16  g_wkb[(size_t)DD * UU];
static __device__ bf16  g_wks[(size_t)DD * UU];
static __device__ bf16  g_wvb[(size_t)DD * UU];
static __device__ bf16  g_wvs[(size_t)DD * UU];
static __device__ bf16  g_wob[(size_t)DD * UU];
static __device__ bf16  g_wos[(size_t)DD * UU];

// ---------------------------------------------------------------------------
// Base-ISA PTX helpers (no sm_103a-only features)
// ---------------------------------------------------------------------------
__device__ __forceinline__ uint32_t smem_u32_of(const void* p) {
    uint32_t a;
    asm("{ .reg .u64 t; cvta.to.shared.u64 t, %1; cvt.u32.u64 %0, t; }"
        : "=r"(a) : "l"(p));
    return a;
}

__device__ __forceinline__ void cp16(uint32_t dst, const void* src) {
    asm volatile("cp.async.cg.shared.global [%0], [%1], 16;"
                 :: "r"(dst), "l"(src) : "memory");
}
__device__ __forceinline__ void cp_commit() {
    asm volatile("cp.async.commit_group;" ::: "memory");
}
template <int N>
__device__ __forceinline__ void cp_wait() {
    asm volatile("cp.async.wait_group %0;" :: "n"(N) : "memory");
}

__device__ __forceinline__ void ldsm4(uint32_t* r, uint32_t addr) {
    asm volatile("ldmatrix.sync.aligned.m8n8.x4.shared.b16 {%0,%1,%2,%3}, [%4];"
                 : "=r"(r[0]), "=r"(r[1]), "=r"(r[2]), "=r"(r[3]) : "r"(addr));
}

__device__ __forceinline__ void mma16816(float* d, const uint32_t* a,
                                         uint32_t b0, uint32_t b1) {
    asm volatile(
        "mma.sync.aligned.m16n8k16.row.col.f32.bf16.bf16.f32 "
        "{%0,%1,%2,%3}, {%4,%5,%6,%7}, {%8,%9}, {%0,%1,%2,%3};"
        : "+f"(d[0]), "+f"(d[1]), "+f"(d[2]), "+f"(d[3])
        : "r"(a[0]), "r"(a[1]), "r"(a[2]), "r"(a[3]), "r"(b0), "r"(b1));
}

// Split a pair of fp32 into packed bf16 big + bf16 small (residual)
__device__ __forceinline__ void split_pair(float x, float y,
                                           uint32_t& big, uint32_t& sml) {
    __nv_bfloat162 b = __floats2bfloat162_rn(x, y);
    float bx = __bfloat162float(b.x), by = __bfloat162float(b.y);
    __nv_bfloat162 s = __floats2bfloat162_rn(x - bx, y - by);
    big = *reinterpret_cast<uint32_t*>(&b);
    sml = *reinterpret_cast<uint32_t*>(&s);
}

// ---------------------------------------------------------------------------
// Per-z operand/output pointer sets (z = blockIdx.z; max 4).
// ---------------------------------------------------------------------------
struct ZPtrs {
    const bf16* Ab[4];
    const bf16* As[4];
    const bf16* Bb[4];
    const bf16* Bs[4];
    float*      C [4];
    bf16*       Ob[4];
    bf16*       Os[4];
};

// ---------------------------------------------------------------------------
// NT GEMM, bf16x3 fp32 emulation:
//   C[M,N] = (Ab+As)[M,K] * (Bb+Bs)[N,K]^T  (3 terms, AsBs dropped)
// Fragment loads are register double-buffered across ks steps so LDS
// latency is covered by the MMA stream (one exposed load per chunk).
// ---------------------------------------------------------------------------
__global__ void __launch_bounds__(256) gemm_bf16x3_kernel(
    ZPtrs zp, const float* __restrict__ scale_ptr,
    const float* __restrict__ bias, int M, int N, int K)
{
    extern __shared__ char smem[];
    const int t  = threadIdx.x;
    const int m0 = blockIdx.y * BM;
    const int n0 = blockIdx.x * BN;
    const int z  = blockIdx.z;

    const char* pAb = (const char*)zp.Ab[z];
    const char* pAs = (const char*)zp.As[z];
    const char* pBb = (const char*)zp.Bb[z];
    const char* pBs = (const char*)zp.Bs[z];

    const uint32_t sbase = smem_u32_of(smem);
    const int nch = K / KC;
    const size_t ldb = (size_t)K * 2;     // row stride in bytes (A and B)

    // producer: 16 cp.async per thread per chunk
    const int prow = t >> 3;              // 0..31
    const int pkg  = t & 7;               // 0..7

#define PRODUCE(ch, st)                                                        \
    do {                                                                       \
        uint32_t s0 = sbase + (st) * STAGE_BYTES;                              \
        size_t colb = (size_t)(ch) * 128 + pkg * 16;                          \
        _Pragma("unroll")                                                      \
        for (int i = 0; i < 4; i++) {                                          \
            int row = i * 32 + prow;                                           \
            uint32_t so = (uint32_t)(row * 128 + ((pkg ^ (row & 7)) << 4));    \
            size_t ga = (size_t)(m0 + row) * ldb + colb;                       \
            size_t gb = (size_t)(n0 + row) * ldb + colb;                       \
            cp16(s0 + so,                  pAb + ga);                          \
            cp16(s0 + TILE_BYTES + so,     pAs + ga);                          \
            cp16(s0 + 2 * TILE_BYTES + so, pBb + gb);                          \
            cp16(s0 + 3 * TILE_BYTES + so, pBs + gb);                          \
        }                                                                      \
        cp_commit();                                                           \
    } while (0)

    PRODUCE(0, 0);
    PRODUCE(1, 1);

    // consumer layout: 8 warps = 2(M) x 4(N); warp tile 64x32
    const int lane = t & 31;
    const int wid  = t >> 5;
    const int wm   = (wid >> 2) * 64;
    const int wn   = (wid & 3) * 32;
    const int lrow = lane & 15;
    const int lkg  = lane >> 4;

    float acc[4][4][4];
#pragma unroll
    for (int i = 0; i < 4; i++)
#pragma unroll
        for (int j = 0; j < 4; j++)
#pragma unroll
            for (int r = 0; r < 4; r++) acc[i][j][r] = 0.0f;

    // double-buffered fragments
    uint32_t a_b[2][4][4], a_s[2][4][4], b_b[2][2][4], b_s[2][2][4];

    // load all fragments for k-group kg into buffer buf
#define LOAD_FRAGS(kg, buf)                                                    \
    do {                                                                       \
        _Pragma("unroll")                                                      \
        for (int mt = 0; mt < 4; mt++) {                                       \
            int r = wm + mt * 16 + lrow;                                       \
            uint32_t off = (uint32_t)(r * 128 + (((kg) ^ (r & 7)) << 4));      \
            ldsm4(a_b[buf][mt], st + off);                                     \
            ldsm4(a_s[buf][mt], st + TILE_BYTES + off);                        \
        }                                                                      \
        _Pragma("unroll")                                                      \
        for (int nt = 0; nt < 2; nt++) {                                       \
            int r = wn + nt * 16 + lrow;                                       \
            uint32_t off = (uint32_t)(r * 128 + (((kg) ^ (r & 7)) << 4));      \
            ldsm4(b_b[buf][nt], st + 2 * TILE_BYTES + off);                    \
            ldsm4(b_s[buf][nt], st + 3 * TILE_BYTES + off);                    \
        }                                                                      \
    } while (0)

    for (int ch = 0; ch < nch; ch++) {
        if (ch + 1 < nch) cp_wait<1>(); else cp_wait<0>();
        __syncthreads();
        if (ch + 2 < nch) PRODUCE(ch + 2, (ch + 2) % STAGES);

        const uint32_t st = sbase + (ch % STAGES) * STAGE_BYTES;

        LOAD_FRAGS(lkg, 0);                      // ks=0 prologue

#pragma unroll
        for (int ks = 0; ks < 4; ks++) {
            const int cur = ks & 1;
            if (ks < 3) {
                const int kg = (ks + 1) * 2 + lkg;
                LOAD_FRAGS(kg, cur ^ 1);         // prefetch next ks
            }
#pragma unroll
            for (int mt = 0; mt < 4; mt++)
#pragma unroll
                for (int nt = 0; nt < 4; nt++) {
                    const uint32_t bb0 = b_b[cur][nt >> 1][nt & 1];
                    const uint32_t bb1 = b_b[cur][nt >> 1][(nt & 1) + 2];
                    const uint32_t bs0 = b_s[cur][nt >> 1][nt & 1];
                    const uint32_t bs1 = b_s[cur][nt >> 1][(nt & 1) + 2];
                    mma16816(acc[mt][nt], a_b[cur][mt], bb0, bb1);  // big*big
                    mma16816(acc[mt][nt], a_b[cur][mt], bs0, bs1);  // big*small
                    mma16816(acc[mt][nt], a_s[cur][mt], bb0, bb1);  // small*big
                }
        }
    }
#undef LOAD_FRAGS
#undef PRODUCE

    // epilogue: c-frag lane l: (m = l/4 [+8], n = 2*(l%4)+{0,1})
    const float scl = scale_ptr ? *scale_ptr : 1.0f;
    float* pC  = zp.C[z];
    bf16*  pOb = zp.Ob[z];
    bf16*  pOs = zp.Os[z];
    const int l4 = lane >> 2;
    const int lc = (lane & 3) * 2;

#pragma unroll
    for (int mt = 0; mt < 4; mt++)
#pragma unroll
        for (int nt = 0; nt < 4; nt++) {
            const int r0  = m0 + wm + mt * 16 + l4;
            const int r1  = r0 + 8;
            const int col = n0 + wn + nt * 8 + lc;
            float v0 = acc[mt][nt][0] * scl;
            float v1 = acc[mt][nt][1] * scl;
            float v2 = acc[mt][nt][2] * scl;
            float v3 = acc[mt][nt][3] * scl;
            if (bias) {
                const float b0 = bias[col], b1 = bias[col + 1];
                v0 += b0; v1 += b1; v2 += b0; v3 += b1;
            }
            if (pC) {
                *(float2*)(pC + (long long)r0 * N + col) = make_float2(v0, v1);
                *(float2*)(pC + (long long)r1 * N + col) = make_float2(v2, v3);
            }
            if (pOb) {
                uint32_t bg, sm;
                split_pair(v0, v1, bg, sm);
                *(uint32_t*)(pOb + (long long)r0 * N + col) = bg;
                *(uint32_t*)(pOs + (long long)r0 * N + col) = sm;
                split_pair(v2, v3, bg, sm);
                *(uint32_t*)(pOb + (long long)r1 * N + col) = bg;
                *(uint32_t*)(pOs + (long long)r1 * N + col) = sm;
            }
        }
}

// ---------------------------------------------------------------------------
// Elementwise fp32 -> bf16 big/small split
// ---------------------------------------------------------------------------
__global__ __launch_bounds__(256) void convert_split_kernel(
    const float* __restrict__ in, bf16* __restrict__ ob, bf16* __restrict__ os)
{
    const long long i = (long long)blockIdx.x * 256 + threadIdx.x; // float4 idx
    float4 v = ((const float4*)in)[i];
    uint32_t b0, s0, b1, s1;
    split_pair(v.x, v.y, b0, s0);
    split_pair(v.z, v.w, b1, s1);
    ((uint2*)ob)[i] = make_uint2(b0, b1);
    ((uint2*)os)[i] = make_uint2(s0, s1);
}

// ---------------------------------------------------------------------------
// Batched 1024x1024 transpose+split for the 4 weight matrices (z selects).
// ---------------------------------------------------------------------------
struct T4Ptrs {
    const float* in[4];
    bf16* ob[4];
    bf16* os[4];
};

__global__ __launch_bounds__(256) void transpose_split4_kernel(T4Ptrs p)
{
    const int z = blockIdx.z;
    const float* in = p.in[z];
    bf16* ob = p.ob[z];
    bf16* os = p.os[z];
    __shared__ float t[32][33];
    const int bx = blockIdx.x * 32;   // n
    const int by = blockIdx.y * 32;   // m
    const int x = threadIdx.x, y = threadIdx.y;
#pragma unroll
    for (int i = 0; i < 32; i += 8)
        t[y + i][x] = in[(long long)(by + y + i) * DD + bx + x];
    __syncthreads();
#pragma unroll
    for (int i = 0; i < 32; i += 8) {
        float v = t[x][y + i];
        bf16 b = __float2bfloat16(v);
        bf16 s = __float2bfloat16(v - __bfloat162float(b));
        const long long o = (long long)(bx + y + i) * DD + by + x;
        ob[o] = b;
        os[o] = s;
    }
}

// ---------------------------------------------------------------------------
// Transpose + split (generic, batched via z): out[n][m] = split(in[m][n])
// ---------------------------------------------------------------------------
__global__ __launch_bounds__(256) void transpose_split_kernel(
    const float* __restrict__ in, bf16* __restrict__ ob, bf16* __restrict__ os,
    int M, int N, long long sIn, long long sOut)
{
    in += (long long)blockIdx.z * sIn;
    ob += (long long)blockIdx.z * sOut;
    os += (long long)blockIdx.z * sOut;
    __shared__ float t[32][33];
    const int bx = blockIdx.x * 32;   // n
    const int by = blockIdx.y * 32;   // m
    const int x = threadIdx.x, y = threadIdx.y;
#pragma unroll
    for (int i = 0; i < 32; i += 8)
        t[y + i][x] = in[(long long)(by + y + i) * N + bx + x];
    __syncthreads();
#pragma unroll
    for (int i = 0; i < 32; i += 8) {
        float v = t[x][y + i];
        bf16 b = __float2bfloat16(v);
        bf16 s = __float2bfloat16(v - __bfloat162float(b));
        const long long o = (long long)(bx + y + i) * M + by + x;
        ob[o] = b;
        os[o] = s;
    }
}

// ---------------------------------------------------------------------------
// Row softmax in-place (fp32) + bf16 big/small split outputs.
// ---------------------------------------------------------------------------
__global__ __launch_bounds__(256) void softmax_split_kernel(
    float* __restrict__ W, bf16* __restrict__ Pb, bf16* __restrict__ Ps)
{
    const long long base = (long long)blockIdx.x * SS;
    float* row = W + base;
    const int t = threadIdx.x;
    __shared__ float red[256];

    float4 a = *(float4*)(row + t * 8);
    float4 b = *(float4*)(row + t * 8 + 4);

    float mx = fmaxf(fmaxf(fmaxf(a.x, a.y), fmaxf(a.z, a.w)),
                     fmaxf(fmaxf(b.x, b.y), fmaxf(b.z, b.w)));
    red[t] = mx;
    __syncthreads();
    for (int s = 128; s > 0; s >>= 1) {
        if (t < s) red[t] = fmaxf(red[t], red[t + s]);
        __syncthreads();
    }
    mx = red[0];
    __syncthreads();

    a.x = __expf(a.x - mx); a.y = __expf(a.y - mx);
    a.z = __expf(a.z - mx); a.w = __expf(a.w - mx);
    b.x = __expf(b.x - mx); b.y = __expf(b.y - mx);
    b.z = __expf(b.z - mx); b.w = __expf(b.w - mx);
    float sum = a.x + a.y + a.z + a.w + b.x + b.y + b.z + b.w;
    red[t] = sum;
    __syncthreads();
    for (int s = 128; s > 0; s >>= 1) {
        if (t < s) red[t] += red[t + s];
        __syncthreads();
    }
    const float inv = 1.0f / red[0];
    a.x *= inv; a.y *= inv; a.z *= inv; a.w *= inv;
    b.x *= inv; b.y *= inv; b.z *= inv; b.w *= inv;

    *(float4*)(row + t * 8)     = a;
    *(float4*)(row + t * 8 + 4) = b;

    uint32_t bg[4], sm[4];
    split_pair(a.x, a.y, bg[0], sm[0]);
    split_pair(a.z, a.w, bg[1], sm[1]);
    split_pair(b.x, b.y, bg[2], sm[2]);
    split_pair(b.z, b.w, bg[3], sm[3]);
    *(uint4*)((char*)Pb + (base + t * 8) * 2) = make_uint4(bg[0], bg[1], bg[2], bg[3]);
    *(uint4*)((char*)Ps + (base + t * 8) * 2) = make_uint4(sm[0], sm[1], sm[2], sm[3]);
}

// ---------------------------------------------------------------------------
// kernel_launch — inputs: inputs, Wq, Wk, Wv, Wo, bo, scale
// output: [output (B*S*D)] [weights (B*S*S)]
// ---------------------------------------------------------------------------
extern "C" void kernel_launch(void* const* d_in, const int* in_sizes, int n_in,
                              void* d_out, int out_size)
{
    (void)in_sizes; (void)n_in; (void)out_size;
    const float* X     = (const float*)d_in[0];
    const float* Wq    = (const float*)d_in[1];
    const float* Wk    = (const float*)d_in[2];
    const float* Wv    = (const float*)d_in[3];
    const float* Wo    = (const float*)d_in[4];
    const float* bo    = (const float*)d_in[5];
    const float* scale = (const float*)d_in[6];

    float* out = (float*)d_out;                     // [B,S,D]
    float* wts = out + (long long)BB * SS * DD;     // [B,S,S]

    bf16 *xb, *xs, *qb, *qs, *kb, *ks, *vtb, *vts, *pb, *ps, *cb, *cs;
    bf16 *wqb, *wqs, *wkb, *wks, *wvb, *wvs, *wob, *wos;
    float* v;
    cudaGetSymbolAddress((void**)&xb,  g_xb);
    cudaGetSymbolAddress((void**)&xs,  g_xs);
    cudaGetSymbolAddress((void**)&qb,  g_qb);
    cudaGetSymbolAddress((void**)&qs,  g_qs);
    cudaGetSymbolAddress((void**)&kb,  g_kb);
    cudaGetSymbolAddress((void**)&ks,  g_ks);
    cudaGetSymbolAddress((void**)&v,   g_v);
    cudaGetSymbolAddress((void**)&vtb, g_vtb);
    cudaGetSymbolAddress((void**)&vts, g_vts);
    cudaGetSymbolAddress((void**)&pb,  g_pb);
    cudaGetSymbolAddress((void**)&ps,  g_ps);
    cudaGetSymbolAddress((void**)&cb,  g_cb);
    cudaGetSymbolAddress((void**)&cs,  g_cs);
    cudaGetSymbolAddress((void**)&wqb, g_wqb);
    cudaGetSymbolAddress((void**)&wqs, g_wqs);
    cudaGetSymbolAddress((void**)&wkb, g_wkb);
    cudaGetSymbolAddress((void**)&wks, g_wks);
    cudaGetSymbolAddress((void**)&wvb, g_wvb);
    cudaGetSymbolAddress((void**)&wvs, g_wvs);
    cudaGetSymbolAddress((void**)&wob, g_wob);
    cudaGetSymbolAddress((void**)&wos, g_wos);

    cudaFuncSetAttribute(gemm_bf16x3_kernel,
                         cudaFuncAttributeMaxDynamicSharedMemorySize, GEMM_SMEM);

    // 1) X split + all 4 weight transposes (one batched launch)
    convert_split_kernel<<<(BB * SS * DD) / (256 * 4), 256>>>(X, xb, xs);
    {
        T4Ptrs tp{};
        tp.in[0] = Wq;  tp.ob[0] = wqb; tp.os[0] = wqs;
        tp.in[1] = Wk;  tp.ob[1] = wkb; tp.os[1] = wks;
        tp.in[2] = Wv;  tp.ob[2] = wvb; tp.os[2] = wvs;
        tp.in[3] = Wo;  tp.ob[3] = wob; tp.os[3] = wos;
        transpose_split4_kernel<<<dim3(32, 32, 4), dim3(32, 8)>>>(tp);
    }

    // 2) Q/K/V projections merged into ONE launch (z selects weights+outputs)
    {
        ZPtrs zp{};
        for (int z = 0; z < 3; z++) { zp.Ab[z] = xb; zp.As[z] = xs; }
        zp.Bb[0] = wqb; zp.Bs[0] = wqs; zp.Ob[0] = qb; zp.Os[0] = qs;
        zp.Bb[1] = wkb; zp.Bs[1] = wks; zp.Ob[1] = kb; zp.Os[1] = ks;
        zp.Bb[2] = wvb; zp.Bs[2] = wvs; zp.C[2]  = v;
        gemm_bf16x3_kernel<<<dim3(UU / BN, (BB * SS) / BM, 3), 256, GEMM_SMEM>>>(
            zp, nullptr, nullptr, BB * SS, UU, DD);
    }

    // 3) scores = (Q @ K^T) * scale -> wts (fp32), batched over B via z
    {
        ZPtrs zp{};
        for (int z = 0; z < BB; z++) {
            zp.Ab[z] = qb + (long long)z * SS * UU;
            zp.As[z] = qs + (long long)z * SS * UU;
            zp.Bb[z] = kb + (long long)z * SS * UU;
            zp.Bs[z] = ks + (long long)z * SS * UU;
            zp.C[z]  = wts + (long long)z * SS * SS;
        }
        gemm_bf16x3_kernel<<<dim3(SS / BN, SS / BM, BB), 256, GEMM_SMEM>>>(
            zp, scale, nullptr, SS, SS, UU);
    }

    // 4) softmax in place + split probs
    softmax_split_kernel<<<BB * SS, 256>>>(wts, pb, ps);

    // 5) transpose V per batch -> vt splits [U,S]
    transpose_split_kernel<<<dim3(UU / 32, SS / 32, BB), dim3(32, 8)>>>(
        v, vtb, vts, SS, UU, (long long)SS * UU, (long long)SS * UU);

    // 6) context = P @ V -> c splits, batched over B via z
    {
        ZPtrs zp{};
        for (int z = 0; z < BB; z++) {
            zp.Ab[z] = pb  + (long long)z * SS * SS;
            zp.As[z] = ps  + (long long)z * SS * SS;
            zp.Bb[z] = vtb + (long long)z * SS * UU;
            zp.Bs[z] = vts + (long long)z * SS * UU;
            zp.Ob[z] = cb  + (long long)z * SS * UU;
            zp.Os[z] = cs  + (long long)z * SS * UU;
        }
        gemm_bf16x3_kernel<<<dim3(UU / BN, SS / BM, BB), 256, GEMM_SMEM>>>(
            zp, nullptr, nullptr, SS, UU, SS);
    }

    // 7) output = context @ Wo + bo
    {
        ZPtrs zp{};
        zp.Ab[0] = cb; zp.As[0] = cs;
        zp.Bb[0] = wob; zp.Bs[0] = wos;
        zp.C[0]  = out;
        gemm_bf16x3_kernel<<<dim3(DD / BN, (BB * SS) / BM, 1), 256, GEMM_SMEM>>>(
            zp, nullptr, bo, BB * SS, DD, UU);
    }
}

// round 16
// speedup vs baseline: 2.6178x; 1.1743x over previous
#include <cuda_runtime.h>
#include <cuda_bf16.h>
#include <math.h>
#include <stdint.h>

// ---------------------------------------------------------------------------
// Problem constants
// ---------------------------------------------------------------------------
#define BB 4
#define SS 2048
#define DD 1024
#define UU 1024

typedef __nv_bfloat16 bf16;

// GEMM tiling: 128x64 CTA tile, 2 CTAs/SM
#define BM 128
#define BN 64
#define KC 64                        // bf16 K elems per chunk (128B rows)
#define STAGES 2
#define A_TILE_BYTES (128 * 128)     // 128 rows x 128B = 16 KB
#define B_TILE_BYTES (64 * 128)      // 64 rows x 128B  = 8 KB
#define OFF_AB 0
#define OFF_AS A_TILE_BYTES
#define OFF_BB (2 * A_TILE_BYTES)
#define OFF_BS (2 * A_TILE_BYTES + B_TILE_BYTES)
#define STAGE_BYTES (2 * A_TILE_BYTES + 2 * B_TILE_BYTES)   // 48 KB
#define GEMM_SMEM (STAGES * STAGE_BYTES)                    // 96 KB

// ---------------------------------------------------------------------------
// Scratch (device globals; allocations are forbidden)
// ---------------------------------------------------------------------------
static __device__ bf16  g_xb [(size_t)BB * SS * DD];
static __device__ bf16  g_xs [(size_t)BB * SS * DD];
static __device__ bf16  g_qb [(size_t)BB * SS * UU];
static __device__ bf16  g_qs [(size_t)BB * SS * UU];
static __device__ bf16  g_kb [(size_t)BB * SS * UU];
static __device__ bf16  g_ks [(size_t)BB * SS * UU];
static __device__ float g_v  [(size_t)BB * SS * UU];
static __device__ bf16  g_vtb[(size_t)BB * SS * UU];
static __device__ bf16  g_vts[(size_t)BB * SS * UU];
static __device__ bf16  g_pb [(size_t)BB * SS * SS];
static __device__ bf16  g_ps [(size_t)BB * SS * SS];
static __device__ bf16  g_cb [(size_t)BB * SS * UU];
static __device__ bf16  g_cs [(size_t)BB * SS * UU];
static __device__ bf16  g_wqb[(size_t)DD * UU];
static __device__ bf16  g_wqs[(size_t)DD * UU];
static __device__ bf16  g_wkb[(size_t)DD * UU];
static __device__ bf16  g_wks[(size_t)DD * UU];
static __device__ bf16  g_wvb[(size_t)DD * UU];
static __device__ bf16  g_wvs[(size_t)DD * UU];
static __device__ bf16  g_wob[(size_t)DD * UU];
static __device__ bf16  g_wos[(size_t)DD * UU];

// ---------------------------------------------------------------------------
// Base-ISA PTX helpers
// ---------------------------------------------------------------------------
__device__ __forceinline__ uint32_t smem_u32_of(const void* p) {
    uint32_t a;
    asm("{ .reg .u64 t; cvta.to.shared.u64 t, %1; cvt.u32.u64 %0, t; }"
        : "=r"(a) : "l"(p));
    return a;
}

__device__ __forceinline__ void cp16(uint32_t dst, const void* src) {
    asm volatile("cp.async.cg.shared.global [%0], [%1], 16;"
                 :: "r"(dst), "l"(src) : "memory");
}
__device__ __forceinline__ void cp_commit() {
    asm volatile("cp.async.commit_group;" ::: "memory");
}
template <int N>
__device__ __forceinline__ void cp_wait() {
    asm volatile("cp.async.wait_group %0;" :: "n"(N) : "memory");
}

__device__ __forceinline__ void ldsm4(uint32_t* r, uint32_t addr) {
    asm volatile("ldmatrix.sync.aligned.m8n8.x4.shared.b16 {%0,%1,%2,%3}, [%4];"
                 : "=r"(r[0]), "=r"(r[1]), "=r"(r[2]), "=r"(r[3]) : "r"(addr));
}

__device__ __forceinline__ void mma16816(float* d, const uint32_t* a,
                                         uint32_t b0, uint32_t b1) {
    asm volatile(
        "mma.sync.aligned.m16n8k16.row.col.f32.bf16.bf16.f32 "
        "{%0,%1,%2,%3}, {%4,%5,%6,%7}, {%8,%9}, {%0,%1,%2,%3};"
        : "+f"(d[0]), "+f"(d[1]), "+f"(d[2]), "+f"(d[3])
        : "r"(a[0]), "r"(a[1]), "r"(a[2]), "r"(a[3]), "r"(b0), "r"(b1));
}

// Split a pair of fp32 into packed bf16 big + bf16 small (residual)
__device__ __forceinline__ void split_pair(float x, float y,
                                           uint32_t& big, uint32_t& sml) {
    __nv_bfloat162 b = __floats2bfloat162_rn(x, y);
    float bx = __bfloat162float(b.x), by = __bfloat162float(b.y);
    __nv_bfloat162 s = __floats2bfloat162_rn(x - bx, y - by);
    big = *reinterpret_cast<uint32_t*>(&b);
    sml = *reinterpret_cast<uint32_t*>(&s);
}

// ---------------------------------------------------------------------------
// Per-z operand/output pointer sets (z = blockIdx.z; max 4).
// ---------------------------------------------------------------------------
struct ZPtrs {
    const bf16* Ab[4];
    const bf16* As[4];
    const bf16* Bb[4];
    const bf16* Bs[4];
    float*      C [4];
    bf16*       Ob[4];
    bf16*       Os[4];
};

// ---------------------------------------------------------------------------
// NT GEMM, bf16x3 fp32 emulation, 128x64 tile, 2 CTAs/SM:
//   C[M,N] = (Ab+As)[M,K] * (Bb+Bs)[N,K]^T  (3 terms, AsBs dropped)
// ---------------------------------------------------------------------------
__global__ void __launch_bounds__(256, 2) gemm_bf16x3_kernel(
    ZPtrs zp, const float* __restrict__ scale_ptr,
    const float* __restrict__ bias, int M, int N, int K)
{
    extern __shared__ char smem[];
    const int t  = threadIdx.x;
    const int m0 = blockIdx.y * BM;
    const int n0 = blockIdx.x * BN;
    const int z  = blockIdx.z;

    const char* pAb = (const char*)zp.Ab[z];
    const char* pAs = (const char*)zp.As[z];
    const char* pBb = (const char*)zp.Bb[z];
    const char* pBs = (const char*)zp.Bs[z];

    const uint32_t sbase = smem_u32_of(smem);
    const int nch = K / KC;
    const size_t ldb = (size_t)K * 2;     // row stride in bytes (A and B)

    // producer: 12 cp.async per thread per chunk (A 8, B 4)
    const int prow = t >> 3;              // 0..31
    const int pkg  = t & 7;               // 0..7

#define PRODUCE(ch, st)                                                        \
    do {                                                                       \
        uint32_t s0 = sbase + (st) * STAGE_BYTES;                              \
        size_t colb = (size_t)(ch) * 128 + pkg * 16;                          \
        _Pragma("unroll")                                                      \
        for (int i = 0; i < 4; i++) {                                          \
            int row = i * 32 + prow;                                           \
            uint32_t so = (uint32_t)(row * 128 + ((pkg ^ (row & 7)) << 4));    \
            size_t ga = (size_t)(m0 + row) * ldb + colb;                       \
            cp16(s0 + OFF_AB + so, pAb + ga);                                  \
            cp16(s0 + OFF_AS + so, pAs + ga);                                  \
        }                                                                      \
        _Pragma("unroll")                                                      \
        for (int i = 0; i < 2; i++) {                                          \
            int row = i * 32 + prow;                                           \
            uint32_t so = (uint32_t)(row * 128 + ((pkg ^ (row & 7)) << 4));    \
            size_t gb = (size_t)(n0 + row) * ldb + colb;                       \
            cp16(s0 + OFF_BB + so, pBb + gb);                                  \
            cp16(s0 + OFF_BS + so, pBs + gb);                                  \
        }                                                                      \
        cp_commit();                                                           \
    } while (0)

    PRODUCE(0, 0);

    // consumer layout: 8 warps = 4(M) x 2(N); warp tile 32x32
    const int lane = t & 31;
    const int wid  = t >> 5;
    const int wm   = (wid >> 1) * 32;
    const int wn   = (wid & 1) * 32;
    const int lrow = lane & 15;
    const int lkg  = lane >> 4;

    float acc[2][4][4];
#pragma unroll
    for (int i = 0; i < 2; i++)
#pragma unroll
        for (int j = 0; j < 4; j++)
#pragma unroll
            for (int r = 0; r < 4; r++) acc[i][j][r] = 0.0f;

    for (int ch = 0; ch < nch; ch++) {
        cp_wait<0>();
        __syncthreads();
        // produce(ch+1) writes stage (ch+1)&1 == (ch-1)&1, last read in
        // iter ch-1; the barrier above orders those reads before this write.
        if (ch + 1 < nch) PRODUCE(ch + 1, (ch + 1) & 1);

        const uint32_t st = sbase + (ch & 1) * STAGE_BYTES;

#pragma unroll
        for (int ks = 0; ks < 4; ks++) {
            const int kg = ks * 2 + lkg;
            uint32_t a_b[2][4], a_s[2][4], b_b[2][4], b_s[2][4];
#pragma unroll
            for (int mt = 0; mt < 2; mt++) {
                int r = wm + mt * 16 + lrow;
                uint32_t off = (uint32_t)(r * 128 + ((kg ^ (r & 7)) << 4));
                ldsm4(a_b[mt], st + OFF_AB + off);
                ldsm4(a_s[mt], st + OFF_AS + off);
            }
#pragma unroll
            for (int nt = 0; nt < 2; nt++) {
                int r = wn + nt * 16 + lrow;
                uint32_t off = (uint32_t)(r * 128 + ((kg ^ (r & 7)) << 4));
                ldsm4(b_b[nt], st + OFF_BB + off);
                ldsm4(b_s[nt], st + OFF_BS + off);
            }
#pragma unroll
            for (int mt = 0; mt < 2; mt++)
#pragma unroll
                for (int nt = 0; nt < 4; nt++) {
                    const uint32_t bb0 = b_b[nt >> 1][nt & 1];
                    const uint32_t bb1 = b_b[nt >> 1][(nt & 1) + 2];
                    const uint32_t bs0 = b_s[nt >> 1][nt & 1];
                    const uint32_t bs1 = b_s[nt >> 1][(nt & 1) + 2];
                    mma16816(acc[mt][nt], a_b[mt], bb0, bb1);   // big*big
                    mma16816(acc[mt][nt], a_b[mt], bs0, bs1);   // big*small
                    mma16816(acc[mt][nt], a_s[mt], bb0, bb1);   // small*big
                }
        }
    }
#undef PRODUCE

    // epilogue: c-frag lane l: (m = l/4 [+8], n = 2*(l%4)+{0,1})
    const float scl = scale_ptr ? *scale_ptr : 1.0f;
    float* pC  = zp.C[z];
    bf16*  pOb = zp.Ob[z];
    bf16*  pOs = zp.Os[z];
    const int l4 = lane >> 2;
    const int lc = (lane & 3) * 2;

#pragma unroll
    for (int mt = 0; mt < 2; mt++)
#pragma unroll
        for (int nt = 0; nt < 4; nt++) {
            const int r0  = m0 + wm + mt * 16 + l4;
            const int r1  = r0 + 8;
            const int col = n0 + wn + nt * 8 + lc;
            float v0 = acc[mt][nt][0] * scl;
            float v1 = acc[mt][nt][1] * scl;
            float v2 = acc[mt][nt][2] * scl;
            float v3 = acc[mt][nt][3] * scl;
            if (bias) {
                const float b0 = bias[col], b1 = bias[col + 1];
                v0 += b0; v1 += b1; v2 += b0; v3 += b1;
            }
            if (pC) {
                *(float2*)(pC + (long long)r0 * N + col) = make_float2(v0, v1);
                *(float2*)(pC + (long long)r1 * N + col) = make_float2(v2, v3);
            }
            if (pOb) {
                uint32_t bg, sm;
                split_pair(v0, v1, bg, sm);
                *(uint32_t*)(pOb + (long long)r0 * N + col) = bg;
                *(uint32_t*)(pOs + (long long)r0 * N + col) = sm;
                split_pair(v2, v3, bg, sm);
                *(uint32_t*)(pOb + (long long)r1 * N + col) = bg;
                *(uint32_t*)(pOs + (long long)r1 * N + col) = sm;
            }
        }
}

// ---------------------------------------------------------------------------
// Elementwise fp32 -> bf16 big/small split
// ---------------------------------------------------------------------------
__global__ __launch_bounds__(256) void convert_split_kernel(
    const float* __restrict__ in, bf16* __restrict__ ob, bf16* __restrict__ os)
{
    const long long i = (long long)blockIdx.x * 256 + threadIdx.x; // float4 idx
    float4 v = ((const float4*)in)[i];
    uint32_t b0, s0, b1, s1;
    split_pair(v.x, v.y, b0, s0);
    split_pair(v.z, v.w, b1, s1);
    ((uint2*)ob)[i] = make_uint2(b0, b1);
    ((uint2*)os)[i] = make_uint2(s0, s1);
}

// ---------------------------------------------------------------------------
// Batched 1024x1024 transpose+split for the 4 weight matrices (z selects).
// ---------------------------------------------------------------------------
struct T4Ptrs {
    const float* in[4];
    bf16* ob[4];
    bf16* os[4];
};

__global__ __launch_bounds__(256) void transpose_split4_kernel(T4Ptrs p)
{
    const int z = blockIdx.z;
    const float* in = p.in[z];
    bf16* ob = p.ob[z];
    bf16* os = p.os[z];
    __shared__ float t[32][33];
    const int bx = blockIdx.x * 32;   // n
    const int by = blockIdx.y * 32;   // m
    const int x = threadIdx.x, y = threadIdx.y;
#pragma unroll
    for (int i = 0; i < 32; i += 8)
        t[y + i][x] = in[(long long)(by + y + i) * DD + bx + x];
    __syncthreads();
#pragma unroll
    for (int i = 0; i < 32; i += 8) {
        float v = t[x][y + i];
        bf16 b = __float2bfloat16(v);
        bf16 s = __float2bfloat16(v - __bfloat162float(b));
        const long long o = (long long)(bx + y + i) * DD + by + x;
        ob[o] = b;
        os[o] = s;
    }
}

// ---------------------------------------------------------------------------
// Transpose + split (generic, batched via z): out[n][m] = split(in[m][n])
// ---------------------------------------------------------------------------
__global__ __launch_bounds__(256) void transpose_split_kernel(
    const float* __restrict__ in, bf16* __restrict__ ob, bf16* __restrict__ os,
    int M, int N, long long sIn, long long sOut)
{
    in += (long long)blockIdx.z * sIn;
    ob += (long long)blockIdx.z * sOut;
    os += (long long)blockIdx.z * sOut;
    __shared__ float t[32][33];
    const int bx = blockIdx.x * 32;   // n
    const int by = blockIdx.y * 32;   // m
    const int x = threadIdx.x, y = threadIdx.y;
#pragma unroll
    for (int i = 0; i < 32; i += 8)
        t[y + i][x] = in[(long long)(by + y + i) * N + bx + x];
    __syncthreads();
#pragma unroll
    for (int i = 0; i < 32; i += 8) {
        float v = t[x][y + i];
        bf16 b = __float2bfloat16(v);
        bf16 s = __float2bfloat16(v - __bfloat162float(b));
        const long long o = (long long)(bx + y + i) * M + by + x;
        ob[o] = b;
        os[o] = s;
    }
}

// ---------------------------------------------------------------------------
// Row softmax in-place (fp32) + bf16 big/small split outputs.
// ---------------------------------------------------------------------------
__global__ __launch_bounds__(256) void softmax_split_kernel(
    float* __restrict__ W, bf16* __restrict__ Pb, bf16* __restrict__ Ps)
{
    const long long base = (long long)blockIdx.x * SS;
    float* row = W + base;
    const int t = threadIdx.x;
    __shared__ float red[256];

    float4 a = *(float4*)(row + t * 8);
    float4 b = *(float4*)(row + t * 8 + 4);

    float mx = fmaxf(fmaxf(fmaxf(a.x, a.y), fmaxf(a.z, a.w)),
                     fmaxf(fmaxf(b.x, b.y), fmaxf(b.z, b.w)));
    red[t] = mx;
    __syncthreads();
    for (int s = 128; s > 0; s >>= 1) {
        if (t < s) red[t] = fmaxf(red[t], red[t + s]);
        __syncthreads();
    }
    mx = red[0];
    __syncthreads();

    a.x = __expf(a.x - mx); a.y = __expf(a.y - mx);
    a.z = __expf(a.z - mx); a.w = __expf(a.w - mx);
    b.x = __expf(b.x - mx); b.y = __expf(b.y - mx);
    b.z = __expf(b.z - mx); b.w = __expf(b.w - mx);
    float sum = a.x + a.y + a.z + a.w + b.x + b.y + b.z + b.w;
    red[t] = sum;
    __syncthreads();
    for (int s = 128; s > 0; s >>= 1) {
        if (t < s) red[t] += red[t + s];
        __syncthreads();
    }
    const float inv = 1.0f / red[0];
    a.x *= inv; a.y *= inv; a.z *= inv; a.w *= inv;
    b.x *= inv; b.y *= inv; b.z *= inv; b.w *= inv;

    *(float4*)(row + t * 8)     = a;
    *(float4*)(row + t * 8 + 4) = b;

    uint32_t bg[4], sm[4];
    split_pair(a.x, a.y, bg[0], sm[0]);
    split_pair(a.z, a.w, bg[1], sm[1]);
    split_pair(b.x, b.y, bg[2], sm[2]);
    split_pair(b.z, b.w, bg[3], sm[3]);
    *(uint4*)((char*)Pb + (base + t * 8) * 2) = make_uint4(bg[0], bg[1], bg[2], bg[3]);
    *(uint4*)((char*)Ps + (base + t * 8) * 2) = make_uint4(sm[0], sm[1], sm[2], sm[3]);
}

// ---------------------------------------------------------------------------
// kernel_launch — inputs: inputs, Wq, Wk, Wv, Wo, bo, scale
// output: [output (B*S*D)] [weights (B*S*S)]
// ---------------------------------------------------------------------------
extern "C" void kernel_launch(void* const* d_in, const int* in_sizes, int n_in,
                              void* d_out, int out_size)
{
    (void)in_sizes; (void)n_in; (void)out_size;
    const float* X     = (const float*)d_in[0];
    const float* Wq    = (const float*)d_in[1];
    const float* Wk    = (const float*)d_in[2];
    const float* Wv    = (const float*)d_in[3];
    const float* Wo    = (const float*)d_in[4];
    const float* bo    = (const float*)d_in[5];
    const float* scale = (const float*)d_in[6];

    float* out = (float*)d_out;                     // [B,S,D]
    float* wts = out + (long long)BB * SS * DD;     // [B,S,S]

    bf16 *xb, *xs, *qb, *qs, *kb, *ks, *vtb, *vts, *pb, *ps, *cb, *cs;
    bf16 *wqb, *wqs, *wkb, *wks, *wvb, *wvs, *wob, *wos;
    float* v;
    cudaGetSymbolAddress((void**)&xb,  g_xb);
    cudaGetSymbolAddress((void**)&xs,  g_xs);
    cudaGetSymbolAddress((void**)&qb,  g_qb);
    cudaGetSymbolAddress((void**)&qs,  g_qs);
    cudaGetSymbolAddress((void**)&kb,  g_kb);
    cudaGetSymbolAddress((void**)&ks,  g_ks);
    cudaGetSymbolAddress((void**)&v,   g_v);
    cudaGetSymbolAddress((void**)&vtb, g_vtb);
    cudaGetSymbolAddress((void**)&vts, g_vts);
    cudaGetSymbolAddress((void**)&pb,  g_pb);
    cudaGetSymbolAddress((void**)&ps,  g_ps);
    cudaGetSymbolAddress((void**)&cb,  g_cb);
    cudaGetSymbolAddress((void**)&cs,  g_cs);
    cudaGetSymbolAddress((void**)&wqb, g_wqb);
    cudaGetSymbolAddress((void**)&wqs, g_wqs);
    cudaGetSymbolAddress((void**)&wkb, g_wkb);
    cudaGetSymbolAddress((void**)&wks, g_wks);
    cudaGetSymbolAddress((void**)&wvb, g_wvb);
    cudaGetSymbolAddress((void**)&wvs, g_wvs);
    cudaGetSymbolAddress((void**)&wob, g_wob);
    cudaGetSymbolAddress((void**)&wos, g_wos);

    cudaFuncSetAttribute(gemm_bf16x3_kernel,
                         cudaFuncAttributeMaxDynamicSharedMemorySize, GEMM_SMEM);

    // 1) X split + all 4 weight transposes (one batched launch)
    convert_split_kernel<<<(BB * SS * DD) / (256 * 4), 256>>>(X, xb, xs);
    {
        T4Ptrs tp{};
        tp.in[0] = Wq;  tp.ob[0] = wqb; tp.os[0] = wqs;
        tp.in[1] = Wk;  tp.ob[1] = wkb; tp.os[1] = wks;
        tp.in[2] = Wv;  tp.ob[2] = wvb; tp.os[2] = wvs;
        tp.in[3] = Wo;  tp.ob[3] = wob; tp.os[3] = wos;
        transpose_split4_kernel<<<dim3(32, 32, 4), dim3(32, 8)>>>(tp);
    }

    // 2) Q/K/V projections merged into ONE launch (z selects weights+outputs)
    {
        ZPtrs zp{};
        for (int z = 0; z < 3; z++) { zp.Ab[z] = xb; zp.As[z] = xs; }
        zp.Bb[0] = wqb; zp.Bs[0] = wqs; zp.Ob[0] = qb; zp.Os[0] = qs;
        zp.Bb[1] = wkb; zp.Bs[1] = wks; zp.Ob[1] = kb; zp.Os[1] = ks;
        zp.Bb[2] = wvb; zp.Bs[2] = wvs; zp.C[2]  = v;
        gemm_bf16x3_kernel<<<dim3(UU / BN, (BB * SS) / BM, 3), 256, GEMM_SMEM>>>(
            zp, nullptr, nullptr, BB * SS, UU, DD);
    }

    // 3) scores = (Q @ K^T) * scale -> wts (fp32), batched over B via z
    {
        ZPtrs zp{};
        for (int z = 0; z < BB; z++) {
            zp.Ab[z] = qb + (long long)z * SS * UU;
            zp.As[z] = qs + (long long)z * SS * UU;
            zp.Bb[z] = kb + (long long)z * SS * UU;
            zp.Bs[z] = ks + (long long)z * SS * UU;
            zp.C[z]  = wts + (long long)z * SS * SS;
        }
        gemm_bf16x3_kernel<<<dim3(SS / BN, SS / BM, BB), 256, GEMM_SMEM>>>(
            zp, scale, nullptr, SS, SS, UU);
    }

    // 4) softmax in place + split probs
    softmax_split_kernel<<<BB * SS, 256>>>(wts, pb, ps);

    // 5) transpose V per batch -> vt splits [U,S]
    transpose_split_kernel<<<dim3(UU / 32, SS / 32, BB), dim3(32, 8)>>>(
        v, vtb, vts, SS, UU, (long long)SS * UU, (long long)SS * UU);

    // 6) context = P @ V -> c splits, batched over B via z
    {
        ZPtrs zp{};
        for (int z = 0; z < BB; z++) {
            zp.Ab[z] = pb  + (long long)z * SS * SS;
            zp.As[z] = ps  + (long long)z * SS * SS;
            zp.Bb[z] = vtb + (long long)z * SS * UU;
            zp.Bs[z] = vts + (long long)z * SS * UU;
            zp.Ob[z] = cb  + (long long)z * SS * UU;
            zp.Os[z] = cs  + (long long)z * SS * UU;
        }
        gemm_bf16x3_kernel<<<dim3(UU / BN, SS / BM, BB), 256, GEMM_SMEM>>>(
            zp, nullptr, nullptr, SS, UU, SS);
    }

    // 7) output = context @ Wo + bo
    {
        ZPtrs zp{};
        zp.Ab[0] = cb; zp.As[0] = cs;
        zp.Bb[0] = wob; zp.Bs[0] = wos;
        zp.C[0]  = out;
        gemm_bf16x3_kernel<<<dim3(DD / BN, (BB * SS) / BM, 1), 256, GEMM_SMEM>>>(
            zp, nullptr, bo, BB * SS, DD, UU);
    }
}

// round 17
// speedup vs baseline: 2.6220x; 1.0016x over previous
#include <cuda_runtime.h>
#include <cuda_bf16.h>
#include <math.h>
#include <stdint.h>

// ---------------------------------------------------------------------------
// Problem constants
// ---------------------------------------------------------------------------
#define BB 4
#define SS 2048
#define DD 1024
#define UU 1024

typedef __nv_bfloat16 bf16;

// GEMM tiling: 128x64 CTA tile, 2 CTAs/SM
#define BM 128
#define BN 64
#define KC 64                        // bf16 K elems per chunk (128B rows)
#define STAGES 2
#define A_TILE_BYTES (128 * 128)     // 128 rows x 128B = 16 KB
#define B_TILE_BYTES (64 * 128)      // 64 rows x 128B  = 8 KB
#define OFF_AB 0
#define OFF_AS A_TILE_BYTES
#define OFF_BB (2 * A_TILE_BYTES)
#define OFF_BS (2 * A_TILE_BYTES + B_TILE_BYTES)
#define STAGE_BYTES (2 * A_TILE_BYTES + 2 * B_TILE_BYTES)   // 48 KB
#define GEMM_SMEM (STAGES * STAGE_BYTES)                    // 96 KB

// ---------------------------------------------------------------------------
// Scratch (device globals; allocations are forbidden)
// ---------------------------------------------------------------------------
static __device__ bf16  g_xb [(size_t)BB * SS * DD];
static __device__ bf16  g_xs [(size_t)BB * SS * DD];
static __device__ bf16  g_qb [(size_t)BB * SS * UU];
static __device__ bf16  g_qs [(size_t)BB * SS * UU];
static __device__ bf16  g_kb [(size_t)BB * SS * UU];
static __device__ bf16  g_ks [(size_t)BB * SS * UU];
static __device__ float g_v  [(size_t)BB * SS * UU];
static __device__ bf16  g_vtb[(size_t)BB * SS * UU];
static __device__ bf16  g_vts[(size_t)BB * SS * UU];
static __device__ bf16  g_pb [(size_t)BB * SS * SS];
static __device__ bf16  g_ps [(size_t)BB * SS * SS];
static __device__ bf16  g_cb [(size_t)BB * SS * UU];
static __device__ bf16  g_cs [(size_t)BB * SS * UU];
static __device__ bf16  g_wqb[(size_t)DD * UU];
static __device__ bf16  g_wqs[(size_t)DD * UU];
static __device__ bf16  g_wkb[(size_t)DD * UU];
static __device__ bf16  g_wks[(size_t)DD * UU];
static __device__ bf16  g_wvb[(size_t)DD * UU];
static __device__ bf16  g_wvs[(size_t)DD * UU];
static __device__ bf16  g_wob[(size_t)DD * UU];
static __device__ bf16  g_wos[(size_t)DD * UU];

// ---------------------------------------------------------------------------
// Base-ISA PTX helpers
// ---------------------------------------------------------------------------
__device__ __forceinline__ uint32_t smem_u32_of(const void* p) {
    uint32_t a;
    asm("{ .reg .u64 t; cvta.to.shared.u64 t, %1; cvt.u32.u64 %0, t; }"
        : "=r"(a) : "l"(p));
    return a;
}

__device__ __forceinline__ void cp16(uint32_t dst, const void* src) {
    asm volatile("cp.async.cg.shared.global [%0], [%1], 16;"
                 :: "r"(dst), "l"(src) : "memory");
}
__device__ __forceinline__ void cp_commit() {
    asm volatile("cp.async.commit_group;" ::: "memory");
}
template <int N>
__device__ __forceinline__ void cp_wait() {
    asm volatile("cp.async.wait_group %0;" :: "n"(N) : "memory");
}

__device__ __forceinline__ void ldsm4(uint32_t* r, uint32_t addr) {
    asm volatile("ldmatrix.sync.aligned.m8n8.x4.shared.b16 {%0,%1,%2,%3}, [%4];"
                 : "=r"(r[0]), "=r"(r[1]), "=r"(r[2]), "=r"(r[3]) : "r"(addr));
}

__device__ __forceinline__ void mma16816(float* d, const uint32_t* a,
                                         uint32_t b0, uint32_t b1) {
    asm volatile(
        "mma.sync.aligned.m16n8k16.row.col.f32.bf16.bf16.f32 "
        "{%0,%1,%2,%3}, {%4,%5,%6,%7}, {%8,%9}, {%0,%1,%2,%3};"
        : "+f"(d[0]), "+f"(d[1]), "+f"(d[2]), "+f"(d[3])
        : "r"(a[0]), "r"(a[1]), "r"(a[2]), "r"(a[3]), "r"(b0), "r"(b1));
}

// Split a pair of fp32 into packed bf16 big + bf16 small (residual)
__device__ __forceinline__ void split_pair(float x, float y,
                                           uint32_t& big, uint32_t& sml) {
    __nv_bfloat162 b = __floats2bfloat162_rn(x, y);
    float bx = __bfloat162float(b.x), by = __bfloat162float(b.y);
    __nv_bfloat162 s = __floats2bfloat162_rn(x - bx, y - by);
    big = *reinterpret_cast<uint32_t*>(&b);
    sml = *reinterpret_cast<uint32_t*>(&s);
}

// ---------------------------------------------------------------------------
// Per-z operand/output pointer sets (z = blockIdx.z; max 4).
// ---------------------------------------------------------------------------
struct ZPtrs {
    const bf16* Ab[4];
    const bf16* As[4];
    const bf16* Bb[4];
    const bf16* Bs[4];
    float*      C [4];
    bf16*       Ob[4];
    bf16*       Os[4];
};

// ---------------------------------------------------------------------------
// NT GEMM, bf16x3 fp32 emulation, 128x64 tile, 2 CTAs/SM:
//   C[M,N] = (Ab+As)[M,K] * (Bb+Bs)[N,K]^T  (3 terms, AsBs dropped)
// ---------------------------------------------------------------------------
__global__ void __launch_bounds__(256, 2) gemm_bf16x3_kernel(
    ZPtrs zp, const float* __restrict__ scale_ptr,
    const float* __restrict__ bias, int M, int N, int K)
{
    extern __shared__ char smem[];
    const int t  = threadIdx.x;
    const int m0 = blockIdx.y * BM;
    const int n0 = blockIdx.x * BN;
    const int z  = blockIdx.z;

    const char* pAb = (const char*)zp.Ab[z];
    const char* pAs = (const char*)zp.As[z];
    const char* pBb = (const char*)zp.Bb[z];
    const char* pBs = (const char*)zp.Bs[z];

    const uint32_t sbase = smem_u32_of(smem);
    const int nch = K / KC;
    const size_t ldb = (size_t)K * 2;     // row stride in bytes (A and B)

    // producer: 12 cp.async per thread per chunk (A 8, B 4)
    const int prow = t >> 3;              // 0..31
    const int pkg  = t & 7;               // 0..7

#define PRODUCE(ch, st)                                                        \
    do {                                                                       \
        uint32_t s0 = sbase + (st) * STAGE_BYTES;                              \
        size_t colb = (size_t)(ch) * 128 + pkg * 16;                          \
        _Pragma("unroll")                                                      \
        for (int i = 0; i < 4; i++) {                                          \
            int row = i * 32 + prow;                                           \
            uint32_t so = (uint32_t)(row * 128 + ((pkg ^ (row & 7)) << 4));    \
            size_t ga = (size_t)(m0 + row) * ldb + colb;                       \
            cp16(s0 + OFF_AB + so, pAb + ga);                                  \
            cp16(s0 + OFF_AS + so, pAs + ga);                                  \
        }                                                                      \
        _Pragma("unroll")                                                      \
        for (int i = 0; i < 2; i++) {                                          \
            int row = i * 32 + prow;                                           \
            uint32_t so = (uint32_t)(row * 128 + ((pkg ^ (row & 7)) << 4));    \
            size_t gb = (size_t)(n0 + row) * ldb + colb;                       \
            cp16(s0 + OFF_BB + so, pBb + gb);                                  \
            cp16(s0 + OFF_BS + so, pBs + gb);                                  \
        }                                                                      \
        cp_commit();                                                           \
    } while (0)

    PRODUCE(0, 0);

    // consumer layout: 8 warps = 4(M) x 2(N); warp tile 32x32
    const int lane = t & 31;
    const int wid  = t >> 5;
    const int wm   = (wid >> 1) * 32;
    const int wn   = (wid & 1) * 32;
    const int lrow = lane & 15;
    const int lkg  = lane >> 4;

    float acc[2][4][4];
#pragma unroll
    for (int i = 0; i < 2; i++)
#pragma unroll
        for (int j = 0; j < 4; j++)
#pragma unroll
            for (int r = 0; r < 4; r++) acc[i][j][r] = 0.0f;

    for (int ch = 0; ch < nch; ch++) {
        cp_wait<0>();
        __syncthreads();
        // produce(ch+1) writes stage (ch+1)&1 == (ch-1)&1, last read in
        // iter ch-1; the barrier above orders those reads before this write.
        if (ch + 1 < nch) PRODUCE(ch + 1, (ch + 1) & 1);

        const uint32_t st = sbase + (ch & 1) * STAGE_BYTES;

#pragma unroll
        for (int ks = 0; ks < 4; ks++) {
            const int kg = ks * 2 + lkg;
            uint32_t a_b[2][4], a_s[2][4], b_b[2][4], b_s[2][4];
#pragma unroll
            for (int mt = 0; mt < 2; mt++) {
                int r = wm + mt * 16 + lrow;
                uint32_t off = (uint32_t)(r * 128 + ((kg ^ (r & 7)) << 4));
                ldsm4(a_b[mt], st + OFF_AB + off);
                ldsm4(a_s[mt], st + OFF_AS + off);
            }
#pragma unroll
            for (int nt = 0; nt < 2; nt++) {
                int r = wn + nt * 16 + lrow;
                uint32_t off = (uint32_t)(r * 128 + ((kg ^ (r & 7)) << 4));
                ldsm4(b_b[nt], st + OFF_BB + off);
                ldsm4(b_s[nt], st + OFF_BS + off);
            }
#pragma unroll
            for (int mt = 0; mt < 2; mt++)
#pragma unroll
                for (int nt = 0; nt < 4; nt++) {
                    const uint32_t bb0 = b_b[nt >> 1][nt & 1];
                    const uint32_t bb1 = b_b[nt >> 1][(nt & 1) + 2];
                    const uint32_t bs0 = b_s[nt >> 1][nt & 1];
                    const uint32_t bs1 = b_s[nt >> 1][(nt & 1) + 2];
                    mma16816(acc[mt][nt], a_b[mt], bb0, bb1);   // big*big
                    mma16816(acc[mt][nt], a_b[mt], bs0, bs1);   // big*small
                    mma16816(acc[mt][nt], a_s[mt], bb0, bb1);   // small*big
                }
        }
    }
#undef PRODUCE

    // epilogue: c-frag lane l: (m = l/4 [+8], n = 2*(l%4)+{0,1})
    const float scl = scale_ptr ? *scale_ptr : 1.0f;
    float* pC  = zp.C[z];
    bf16*  pOb = zp.Ob[z];
    bf16*  pOs = zp.Os[z];
    const int l4 = lane >> 2;
    const int lc = (lane & 3) * 2;

#pragma unroll
    for (int mt = 0; mt < 2; mt++)
#pragma unroll
        for (int nt = 0; nt < 4; nt++) {
            const int r0  = m0 + wm + mt * 16 + l4;
            const int r1  = r0 + 8;
            const int col = n0 + wn + nt * 8 + lc;
            float v0 = acc[mt][nt][0] * scl;
            float v1 = acc[mt][nt][1] * scl;
            float v2 = acc[mt][nt][2] * scl;
            float v3 = acc[mt][nt][3] * scl;
            if (bias) {
                const float b0 = bias[col], b1 = bias[col + 1];
                v0 += b0; v1 += b1; v2 += b0; v3 += b1;
            }
            if (pC) {
                *(float2*)(pC + (long long)r0 * N + col) = make_float2(v0, v1);
                *(float2*)(pC + (long long)r1 * N + col) = make_float2(v2, v3);
            }
            if (pOb) {
                uint32_t bg, sm;
                split_pair(v0, v1, bg, sm);
                *(uint32_t*)(pOb + (long long)r0 * N + col) = bg;
                *(uint32_t*)(pOs + (long long)r0 * N + col) = sm;
                split_pair(v2, v3, bg, sm);
                *(uint32_t*)(pOb + (long long)r1 * N + col) = bg;
                *(uint32_t*)(pOs + (long long)r1 * N + col) = sm;
            }
        }
}

// ---------------------------------------------------------------------------
// Elementwise fp32 -> bf16 big/small split
// ---------------------------------------------------------------------------
__global__ __launch_bounds__(256) void convert_split_kernel(
    const float* __restrict__ in, bf16* __restrict__ ob, bf16* __restrict__ os)
{
    const long long i = (long long)blockIdx.x * 256 + threadIdx.x; // float4 idx
    float4 v = ((const float4*)in)[i];
    uint32_t b0, s0, b1, s1;
    split_pair(v.x, v.y, b0, s0);
    split_pair(v.z, v.w, b1, s1);
    ((uint2*)ob)[i] = make_uint2(b0, b1);
    ((uint2*)os)[i] = make_uint2(s0, s1);
}

// ---------------------------------------------------------------------------
// Batched 1024x1024 transpose+split for the 4 weight matrices (z selects).
// ---------------------------------------------------------------------------
struct T4Ptrs {
    const float* in[4];
    bf16* ob[4];
    bf16* os[4];
};

__global__ __launch_bounds__(256) void transpose_split4_kernel(T4Ptrs p)
{
    const int z = blockIdx.z;
    const float* in = p.in[z];
    bf16* ob = p.ob[z];
    bf16* os = p.os[z];
    __shared__ float t[32][33];
    const int bx = blockIdx.x * 32;   // n
    const int by = blockIdx.y * 32;   // m
    const int x = threadIdx.x, y = threadIdx.y;
#pragma unroll
    for (int i = 0; i < 32; i += 8)
        t[y + i][x] = in[(long long)(by + y + i) * DD + bx + x];
    __syncthreads();
#pragma unroll
    for (int i = 0; i < 32; i += 8) {
        float v = t[x][y + i];
        bf16 b = __float2bfloat16(v);
        bf16 s = __float2bfloat16(v - __bfloat162float(b));
        const long long o = (long long)(bx + y + i) * DD + by + x;
        ob[o] = b;
        os[o] = s;
    }
}

// ---------------------------------------------------------------------------
// Transpose + split (generic, batched via z): out[n][m] = split(in[m][n])
// ---------------------------------------------------------------------------
__global__ __launch_bounds__(256) void transpose_split_kernel(
    const float* __restrict__ in, bf16* __restrict__ ob, bf16* __restrict__ os,
    int M, int N, long long sIn, long long sOut)
{
    in += (long long)blockIdx.z * sIn;
    ob += (long long)blockIdx.z * sOut;
    os += (long long)blockIdx.z * sOut;
    __shared__ float t[32][33];
    const int bx = blockIdx.x * 32;   // n
    const int by = blockIdx.y * 32;   // m
    const int x = threadIdx.x, y = threadIdx.y;
#pragma unroll
    for (int i = 0; i < 32; i += 8)
        t[y + i][x] = in[(long long)(by + y + i) * N + bx + x];
    __syncthreads();
#pragma unroll
    for (int i = 0; i < 32; i += 8) {
        float v = t[x][y + i];
        bf16 b = __float2bfloat16(v);
        bf16 s = __float2bfloat16(v - __bfloat162float(b));
        const long long o = (long long)(bx + y + i) * M + by + x;
        ob[o] = b;
        os[o] = s;
    }
}

// ---------------------------------------------------------------------------
// Row softmax in-place (fp32) + bf16 big/small split outputs.
// ---------------------------------------------------------------------------
__global__ __launch_bounds__(256) void softmax_split_kernel(
    float* __restrict__ W, bf16* __restrict__ Pb, bf16* __restrict__ Ps)
{
    const long long base = (long long)blockIdx.x * SS;
    float* row = W + base;
    const int t = threadIdx.x;
    __shared__ float red[256];

    float4 a = *(float4*)(row + t * 8);
    float4 b = *(float4*)(row + t * 8 + 4);

    float mx = fmaxf(fmaxf(fmaxf(a.x, a.y), fmaxf(a.z, a.w)),
                     fmaxf(fmaxf(b.x, b.y), fmaxf(b.z, b.w)));
    red[t] = mx;
    __syncthreads();
    for (int s = 128; s > 0; s >>= 1) {
        if (t < s) red[t] = fmaxf(red[t], red[t + s]);
        __syncthreads();
    }
    mx = red[0];
    __syncthreads();

    a.x = __expf(a.x - mx); a.y = __expf(a.y - mx);
    a.z = __expf(a.z - mx); a.w = __expf(a.w - mx);
    b.x = __expf(b.x - mx); b.y = __expf(b.y - mx);
    b.z = __expf(b.z - mx); b.w = __expf(b.w - mx);
    float sum = a.x + a.y + a.z + a.w + b.x + b.y + b.z + b.w;
    red[t] = sum;
    __syncthreads();
    for (int s = 128; s > 0; s >>= 1) {
        if (t < s) red[t] += red[t + s];
        __syncthreads();
    }
    const float inv = 1.0f / red[0];
    a.x *= inv; a.y *= inv; a.z *= inv; a.w *= inv;
    b.x *= inv; b.y *= inv; b.z *= inv; b.w *= inv;

    *(float4*)(row + t * 8)     = a;
    *(float4*)(row + t * 8 + 4) = b;

    uint32_t bg[4], sm[4];
    split_pair(a.x, a.y, bg[0], sm[0]);
    split_pair(a.z, a.w, bg[1], sm[1]);
    split_pair(b.x, b.y, bg[2], sm[2]);
    split_pair(b.z, b.w, bg[3], sm[3]);
    *(uint4*)((char*)Pb + (base + t * 8) * 2) = make_uint4(bg[0], bg[1], bg[2], bg[3]);
    *(uint4*)((char*)Ps + (base + t * 8) * 2) = make_uint4(sm[0], sm[1], sm[2], sm[3]);
}

// ---------------------------------------------------------------------------
// kernel_launch — inputs: inputs, Wq, Wk, Wv, Wo, bo, scale
// output: [output (B*S*D)] [weights (B*S*S)]
// ---------------------------------------------------------------------------
extern "C" void kernel_launch(void* const* d_in, const int* in_sizes, int n_in,
                              void* d_out, int out_size)
{
    (void)in_sizes; (void)n_in; (void)out_size;
    const float* X     = (const float*)d_in[0];
    const float* Wq    = (const float*)d_in[1];
    const float* Wk    = (const float*)d_in[2];
    const float* Wv    = (const float*)d_in[3];
    const float* Wo    = (const float*)d_in[4];
    const float* bo    = (const float*)d_in[5];
    const float* scale = (const float*)d_in[6];

    float* out = (float*)d_out;                     // [B,S,D]
    float* wts = out + (long long)BB * SS * DD;     // [B,S,S]

    bf16 *xb, *xs, *qb, *qs, *kb, *ks, *vtb, *vts, *pb, *ps, *cb, *cs;
    bf16 *wqb, *wqs, *wkb, *wks, *wvb, *wvs, *wob, *wos;
    float* v;
    cudaGetSymbolAddress((void**)&xb,  g_xb);
    cudaGetSymbolAddress((void**)&xs,  g_xs);
    cudaGetSymbolAddress((void**)&qb,  g_qb);
    cudaGetSymbolAddress((void**)&qs,  g_qs);
    cudaGetSymbolAddress((void**)&kb,  g_kb);
    cudaGetSymbolAddress((void**)&ks,  g_ks);
    cudaGetSymbolAddress((void**)&v,   g_v);
    cudaGetSymbolAddress((void**)&vtb, g_vtb);
    cudaGetSymbolAddress((void**)&vts, g_vts);
    cudaGetSymbolAddress((void**)&pb,  g_pb);
    cudaGetSymbolAddress((void**)&ps,  g_ps);
    cudaGetSymbolAddress((void**)&cb,  g_cb);
    cudaGetSymbolAddress((void**)&cs,  g_cs);
    cudaGetSymbolAddress((void**)&wqb, g_wqb);
    cudaGetSymbolAddress((void**)&wqs, g_wqs);
    cudaGetSymbolAddress((void**)&wkb, g_wkb);
    cudaGetSymbolAddress((void**)&wks, g_wks);
    cudaGetSymbolAddress((void**)&wvb, g_wvb);
    cudaGetSymbolAddress((void**)&wvs, g_wvs);
    cudaGetSymbolAddress((void**)&wob, g_wob);
    cudaGetSymbolAddress((void**)&wos, g_wos);

    cudaFuncSetAttribute(gemm_bf16x3_kernel,
                         cudaFuncAttributeMaxDynamicSharedMemorySize, GEMM_SMEM);

    // 1) X split + all 4 weight transposes (one batched launch)
    convert_split_kernel<<<(BB * SS * DD) / (256 * 4), 256>>>(X, xb, xs);
    {
        T4Ptrs tp{};
        tp.in[0] = Wq;  tp.ob[0] = wqb; tp.os[0] = wqs;
        tp.in[1] = Wk;  tp.ob[1] = wkb; tp.os[1] = wks;
        tp.in[2] = Wv;  tp.ob[2] = wvb; tp.os[2] = wvs;
        tp.in[3] = Wo;  tp.ob[3] = wob; tp.os[3] = wos;
        transpose_split4_kernel<<<dim3(32, 32, 4), dim3(32, 8)>>>(tp);
    }

    // 2) Q/K/V projections merged into ONE launch (z selects weights+outputs)
    {
        ZPtrs zp{};
        for (int z = 0; z < 3; z++) { zp.Ab[z] = xb; zp.As[z] = xs; }
        zp.Bb[0] = wqb; zp.Bs[0] = wqs; zp.Ob[0] = qb; zp.Os[0] = qs;
        zp.Bb[1] = wkb; zp.Bs[1] = wks; zp.Ob[1] = kb; zp.Os[1] = ks;
        zp.Bb[2] = wvb; zp.Bs[2] = wvs; zp.C[2]  = v;
        gemm_bf16x3_kernel<<<dim3(UU / BN, (BB * SS) / BM, 3), 256, GEMM_SMEM>>>(
            zp, nullptr, nullptr, BB * SS, UU, DD);
    }

    // 3) scores = (Q @ K^T) * scale -> wts (fp32), batched over B via z
    {
        ZPtrs zp{};
        for (int z = 0; z < BB; z++) {
            zp.Ab[z] = qb + (long long)z * SS * UU;
            zp.As[z] = qs + (long long)z * SS * UU;
            zp.Bb[z] = kb + (long long)z * SS * UU;
            zp.Bs[z] = ks + (long long)z * SS * UU;
            zp.C[z]  = wts + (long long)z * SS * SS;
        }
        gemm_bf16x3_kernel<<<dim3(SS / BN, SS / BM, BB), 256, GEMM_SMEM>>>(
            zp, scale, nullptr, SS, SS, UU);
    }

    // 4) softmax in place + split probs
    softmax_split_kernel<<<BB * SS, 256>>>(wts, pb, ps);

    // 5) transpose V per batch -> vt splits [U,S]
    transpose_split_kernel<<<dim3(UU / 32, SS / 32, BB), dim3(32, 8)>>>(
        v, vtb, vts, SS, UU, (long long)SS * UU, (long long)SS * UU);

    // 6) context = P @ V -> c splits, batched over B via z
    {
        ZPtrs zp{};
        for (int z = 0; z < BB; z++) {
            zp.Ab[z] = pb  + (long long)z * SS * SS;
            zp.As[z] = ps  + (long long)z * SS * SS;
            zp.Bb[z] = vtb + (long long)z * SS * UU;
            zp.Bs[z] = vts + (long long)z * SS * UU;
            zp.Ob[z] = cb  + (long long)z * SS * UU;
            zp.Os[z] = cs  + (long long)z * SS * UU;
        }
        gemm_bf16x3_kernel<<<dim3(UU / BN, SS / BM, BB), 256, GEMM_SMEM>>>(
            zp, nullptr, nullptr, SS, UU, SS);
    }

    // 7) output = context @ Wo + bo
    {
        ZPtrs zp{};
        zp.Ab[0] = cb; zp.As[0] = cs;
        zp.Bb[0] = wob; zp.Bs[0] = wos;
        zp.C[0]  = out;
        gemm_bf16x3_kernel<<<dim3(DD / BN, (BB * SS) / BM, 1), 256, GEMM_SMEM>>>(
            zp, nullptr, bo, BB * SS, DD, UU);
    }
}